// round 12
// baseline (speedup 1.0000x reference)
#include <cuda_runtime.h>
#include <math.h>

// ---------------- problem constants ----------------
#define LNUM 13
#define DM   512
#define HN   8
#define DKN  64
#define DFFN 1920
#define NN2  (2*DFFN)
#define TN   64
#define BN_  512
#define MT   (BN_*TN)          // 32768 tokens

// ---------------- scratch (device globals; no allocs allowed) ----------------
__device__ float g_h[16777216];   // MT*DM   (post-LN activations)
__device__ float g_q[16777216];
__device__ float g_k[16777216];
__device__ float g_v[16777216];
__device__ float g_c[16777216];   // attention context
__device__ float g_g[62914560];   // MT*DFFN (gated FFN intermediate)

// ---------------- helpers ----------------
__device__ __forceinline__ unsigned f2tf(float x) {
    unsigned r; asm("cvt.rna.tf32.f32 %0, %1;" : "=r"(r) : "f"(x)); return r;
}
__device__ __forceinline__ uint4 cvt4(float4 v) {
    return make_uint4(f2tf(v.x), f2tf(v.y), f2tf(v.z), f2tf(v.w));
}
__device__ __forceinline__ void mma8(float c[4], const unsigned a[4],
                                     unsigned b0, unsigned b1) {
    asm volatile(
        "mma.sync.aligned.m16n8k8.row.col.f32.tf32.tf32.f32 "
        "{%0,%1,%2,%3}, {%4,%5,%6,%7}, {%8,%9}, {%0,%1,%2,%3};\n"
        : "+f"(c[0]), "+f"(c[1]), "+f"(c[2]), "+f"(c[3])
        : "r"(a[0]), "r"(a[1]), "r"(a[2]), "r"(a[3]), "r"(b0), "r"(b1));
}
__device__ __forceinline__ float gelu_exact(float x) {
    return 0.5f * x * (1.0f + erff(x * 0.70710678118654752f));
}

// ---------------- LayerNorm: one block (128 thr) per token row of 512 ----------------
__global__ void ln_kernel(const float* __restrict__ x, const float* __restrict__ w,
                          const float* __restrict__ b, float* __restrict__ out) {
    const int row = blockIdx.x;
    const int tid = threadIdx.x;
    const float4 v = reinterpret_cast<const float4*>(x + (size_t)row * DM)[tid];
    float s  = v.x + v.y + v.z + v.w;
    float ss = v.x*v.x + v.y*v.y + v.z*v.z + v.w*v.w;
    #pragma unroll
    for (int o = 16; o > 0; o >>= 1) {
        s  += __shfl_xor_sync(0xffffffffu, s,  o);
        ss += __shfl_xor_sync(0xffffffffu, ss, o);
    }
    __shared__ float sh[8];
    const int wid = tid >> 5;
    if ((tid & 31) == 0) { sh[wid] = s; sh[4 + wid] = ss; }
    __syncthreads();
    s  = sh[0] + sh[1] + sh[2] + sh[3];
    ss = sh[4] + sh[5] + sh[6] + sh[7];
    const float mean = s * (1.0f / DM);
    const float var  = ss * (1.0f / DM) - mean * mean;
    const float inv  = rsqrtf(var + 1e-5f);
    const float4 wv = reinterpret_cast<const float4*>(w)[tid];
    const float4 bv = reinterpret_cast<const float4*>(b)[tid];
    float4 o;
    o.x = (v.x - mean) * inv * wv.x + bv.x;
    o.y = (v.y - mean) * inv * wv.y + bv.y;
    o.z = (v.z - mean) * inv * wv.z + bv.z;
    o.w = (v.w - mean) * inv * wv.w + bv.w;
    reinterpret_cast<float4*>(out + (size_t)row * DM)[tid] = o;
}

// ---------------- generic tf32 GEMM: C = A(MxK,lda) @ W(KxN) + bias [+C] ----------------
// tile 128x128x32, 256 threads (8 warps as 2Mx4N), thread tile = 16 mma frags
template<int MODE>  // 0: overwrite, 1: residual accumulate into C
__global__ void __launch_bounds__(256, 2) gemm_tf32(
    const float* __restrict__ A, const float* __restrict__ W,
    const float* __restrict__ bias, float* __restrict__ C,
    int N, int K, int lda) {
    __shared__ unsigned As[128 * 36];   // [m][k], stride 36 (≡4 mod 32: gid*4+tig bijective)
    __shared__ unsigned Ws[32 * 136];   // [k][n], stride 136 (≡8 mod 32: tig*8+gid bijective)
    const int tid  = threadIdx.x;
    const int m0   = blockIdx.y * 128;
    const int n0   = blockIdx.x * 128;
    const int w    = tid >> 5, lane = tid & 31, gid = lane >> 2, tig = lane & 3;
    const int wm   = (w & 1) * 64, wn = (w >> 1) * 32;

    float acc[4][4][4];
    #pragma unroll
    for (int i = 0; i < 4; i++)
        #pragma unroll
        for (int j = 0; j < 4; j++)
            #pragma unroll
            for (int r = 0; r < 4; r++) acc[i][j][r] = 0.0f;

    for (int kb = 0; kb < K; kb += 32) {
        #pragma unroll
        for (int j = 0; j < 4; j++) {
            int lin = tid + j * 256;
            int mm = lin >> 3, k4 = (lin & 7) << 2;
            float4 va = *reinterpret_cast<const float4*>(A + (size_t)(m0 + mm) * lda + kb + k4);
            *reinterpret_cast<uint4*>(&As[mm * 36 + k4]) = cvt4(va);
        }
        #pragma unroll
        for (int j = 0; j < 4; j++) {
            int lin = tid + j * 256;
            int kk = lin >> 5, n4 = (lin & 31) << 2;
            float4 vb = *reinterpret_cast<const float4*>(W + (size_t)(kb + kk) * N + n0 + n4);
            *reinterpret_cast<uint4*>(&Ws[kk * 136 + n4]) = cvt4(vb);
        }
        __syncthreads();
        #pragma unroll
        for (int ks = 0; ks < 4; ks++) {
            const int k0 = ks * 8;
            unsigned a[4][4];
            #pragma unroll
            for (int mi = 0; mi < 4; mi++) {
                int r0 = wm + mi * 16 + gid;
                a[mi][0] = As[r0 * 36 + k0 + tig];
                a[mi][1] = As[(r0 + 8) * 36 + k0 + tig];
                a[mi][2] = As[r0 * 36 + k0 + tig + 4];
                a[mi][3] = As[(r0 + 8) * 36 + k0 + tig + 4];
            }
            #pragma unroll
            for (int ni = 0; ni < 4; ni++) {
                unsigned b0 = Ws[(k0 + tig) * 136 + wn + ni * 8 + gid];
                unsigned b1 = Ws[(k0 + tig + 4) * 136 + wn + ni * 8 + gid];
                #pragma unroll
                for (int mi = 0; mi < 4; mi++) mma8(acc[mi][ni], a[mi], b0, b1);
            }
        }
        __syncthreads();
    }
    #pragma unroll
    for (int mi = 0; mi < 4; mi++) {
        #pragma unroll
        for (int ni = 0; ni < 4; ni++) {
            int row = m0 + wm + mi * 16 + gid;
            int col = n0 + wn + ni * 8 + tig * 2;
            float2 bv = *reinterpret_cast<const float2*>(bias + col);
            float* p0 = C + (size_t)row * N + col;
            float* p1 = C + (size_t)(row + 8) * N + col;
            float v0 = acc[mi][ni][0] + bv.x, v1 = acc[mi][ni][1] + bv.y;
            float v2 = acc[mi][ni][2] + bv.x, v3 = acc[mi][ni][3] + bv.y;
            if (MODE == 1) {
                float2 o0 = *reinterpret_cast<float2*>(p0);
                float2 o1 = *reinterpret_cast<float2*>(p1);
                v0 += o0.x; v1 += o0.y; v2 += o1.x; v3 += o1.y;
            }
            *reinterpret_cast<float2*>(p0) = make_float2(v0, v1);
            *reinterpret_cast<float2*>(p1) = make_float2(v2, v3);
        }
    }
}

// ---------------- fused dual-GEMM + GLU: G = gelu(A@Wp[:, :DFF]+bp1) * (A@Wp[:, DFF:]+bp2)
// tile 128 x (64 per half) x 32; never materializes pr (saves 1 GB/layer traffic)
__global__ void __launch_bounds__(256, 2) glu_gemm(
    const float* __restrict__ A, const float* __restrict__ Wp,
    const float* __restrict__ bp, float* __restrict__ G) {
    __shared__ unsigned As[128 * 36];
    __shared__ unsigned W1[32 * 72];   // stride 72 ≡ 8 mod 32 → conflict-free B reads
    __shared__ unsigned W2[32 * 72];
    const int tid = threadIdx.x;
    const int m0  = blockIdx.y * 128;
    const int n0  = blockIdx.x * 64;
    const int w   = tid >> 5, lane = tid & 31, gid = lane >> 2, tig = lane & 3;
    const int wm  = (w & 1) * 64, wn = (w >> 1) * 16;

    float ac1[4][2][4], ac2[4][2][4];
    #pragma unroll
    for (int i = 0; i < 4; i++)
        #pragma unroll
        for (int j = 0; j < 2; j++)
            #pragma unroll
            for (int r = 0; r < 4; r++) { ac1[i][j][r] = 0.0f; ac2[i][j][r] = 0.0f; }

    for (int kb = 0; kb < DM; kb += 32) {
        #pragma unroll
        for (int j = 0; j < 4; j++) {
            int lin = tid + j * 256;
            int mm = lin >> 3, k4 = (lin & 7) << 2;
            float4 va = *reinterpret_cast<const float4*>(A + (size_t)(m0 + mm) * DM + kb + k4);
            *reinterpret_cast<uint4*>(&As[mm * 36 + k4]) = cvt4(va);
        }
        #pragma unroll
        for (int j = 0; j < 2; j++) {
            int lin = tid + j * 256;
            int kk = lin >> 4, n4 = (lin & 15) << 2;
            const float* wrow = Wp + (size_t)(kb + kk) * NN2 + n0 + n4;
            float4 v1 = *reinterpret_cast<const float4*>(wrow);
            float4 v2 = *reinterpret_cast<const float4*>(wrow + DFFN);
            *reinterpret_cast<uint4*>(&W1[kk * 72 + n4]) = cvt4(v1);
            *reinterpret_cast<uint4*>(&W2[kk * 72 + n4]) = cvt4(v2);
        }
        __syncthreads();
        #pragma unroll
        for (int ks = 0; ks < 4; ks++) {
            const int k0 = ks * 8;
            unsigned a[4][4];
            #pragma unroll
            for (int mi = 0; mi < 4; mi++) {
                int r0 = wm + mi * 16 + gid;
                a[mi][0] = As[r0 * 36 + k0 + tig];
                a[mi][1] = As[(r0 + 8) * 36 + k0 + tig];
                a[mi][2] = As[r0 * 36 + k0 + tig + 4];
                a[mi][3] = As[(r0 + 8) * 36 + k0 + tig + 4];
            }
            #pragma unroll
            for (int ni = 0; ni < 2; ni++) {
                int cb = wn + ni * 8 + gid;
                unsigned b0 = W1[(k0 + tig) * 72 + cb];
                unsigned b1 = W1[(k0 + tig + 4) * 72 + cb];
                #pragma unroll
                for (int mi = 0; mi < 4; mi++) mma8(ac1[mi][ni], a[mi], b0, b1);
                unsigned c0 = W2[(k0 + tig) * 72 + cb];
                unsigned c1 = W2[(k0 + tig + 4) * 72 + cb];
                #pragma unroll
                for (int mi = 0; mi < 4; mi++) mma8(ac2[mi][ni], a[mi], c0, c1);
            }
        }
        __syncthreads();
    }
    #pragma unroll
    for (int mi = 0; mi < 4; mi++) {
        #pragma unroll
        for (int ni = 0; ni < 2; ni++) {
            int row = m0 + wm + mi * 16 + gid;
            int col = n0 + wn + ni * 8 + tig * 2;
            float2 b1 = *reinterpret_cast<const float2*>(bp + col);
            float2 b2 = *reinterpret_cast<const float2*>(bp + DFFN + col);
            float g0 = gelu_exact(ac1[mi][ni][0] + b1.x) * (ac2[mi][ni][0] + b2.x);
            float g1 = gelu_exact(ac1[mi][ni][1] + b1.y) * (ac2[mi][ni][1] + b2.y);
            float g2 = gelu_exact(ac1[mi][ni][2] + b1.x) * (ac2[mi][ni][2] + b2.x);
            float g3 = gelu_exact(ac1[mi][ni][3] + b1.y) * (ac2[mi][ni][3] + b2.y);
            *reinterpret_cast<float2*>(G + (size_t)row * DFFN + col)       = make_float2(g0, g1);
            *reinterpret_cast<float2*>(G + (size_t)(row + 8) * DFFN + col) = make_float2(g2, g3);
        }
    }
}

// ---------------- fused attention: one CTA per (b, h) ----------------
// S = QK^T/8 + 2*tanh(rel_bias), clamp ±50, softmax, ctx = P V — all via tf32 mma
#define AST 68   // Q/K/P smem row stride (≡4 mod 32)
#define VST 72   // V smem row stride (≡8 mod 32)
#define ASMEM_WORDS (64*AST*3 + 64*VST + 240)
__global__ void __launch_bounds__(128) attn_kernel(
    const float* __restrict__ q, const float* __restrict__ k,
    const float* __restrict__ v, const float* __restrict__ tab,
    float* __restrict__ ctx) {
    extern __shared__ float smf[];
    unsigned* Qs = reinterpret_cast<unsigned*>(smf);
    unsigned* Ks = Qs + 64 * AST;
    unsigned* Vs = Ks + 64 * AST;
    float*    Ps = reinterpret_cast<float*>(Vs + 64 * VST);
    float*    Bs = Ps + 64 * AST;

    const int hh = blockIdx.x, bb = blockIdx.y;
    const int tid = threadIdx.x;
    const size_t base = ((size_t)bb * TN) * DM + hh * DKN;

    #pragma unroll
    for (int i = 0; i < 8; i++) {
        int lin = tid + i * 128;
        int t = lin >> 4, d4 = (lin & 15) << 2;
        float4 vq = *reinterpret_cast<const float4*>(q + base + (size_t)t * DM + d4);
        float4 vk = *reinterpret_cast<const float4*>(k + base + (size_t)t * DM + d4);
        float4 vv = *reinterpret_cast<const float4*>(v + base + (size_t)t * DM + d4);
        *reinterpret_cast<uint4*>(&Qs[t * AST + d4]) = cvt4(vq);
        *reinterpret_cast<uint4*>(&Ks[t * AST + d4]) = cvt4(vk);
        *reinterpret_cast<uint4*>(&Vs[t * VST + d4]) = cvt4(vv);
    }
    for (int i = tid; i < 225; i += 128)
        Bs[i] = 2.0f * tanhf(tab[(size_t)i * HN + hh]);
    __syncthreads();

    const int w = tid >> 5, lane = tid & 31, gid = lane >> 2, tig = lane & 3;

    // ---- S = Q K^T ----
    float sacc[8][4];
    #pragma unroll
    for (int i = 0; i < 8; i++)
        #pragma unroll
        for (int r = 0; r < 4; r++) sacc[i][r] = 0.0f;
    #pragma unroll
    for (int ks = 0; ks < 8; ks++) {
        const int k0 = ks * 8;
        unsigned a[4];
        a[0] = Qs[(w * 16 + gid) * AST + k0 + tig];
        a[1] = Qs[(w * 16 + gid + 8) * AST + k0 + tig];
        a[2] = Qs[(w * 16 + gid) * AST + k0 + tig + 4];
        a[3] = Qs[(w * 16 + gid + 8) * AST + k0 + tig + 4];
        #pragma unroll
        for (int ni = 0; ni < 8; ni++) {
            unsigned b0 = Ks[(ni * 8 + gid) * AST + k0 + tig];
            unsigned b1 = Ks[(ni * 8 + gid) * AST + k0 + tig + 4];
            mma8(sacc[ni], a, b0, b1);
        }
    }
    // scores epilogue: scale, rel bias, clamp → Ps
    #pragma unroll
    for (int ni = 0; ni < 8; ni++) {
        int t0 = w * 16 + gid;
        int s0 = ni * 8 + tig * 2;
        #pragma unroll
        for (int r = 0; r < 4; r++) {
            int t = t0 + (r >> 1) * 8;
            int s = s0 + (r & 1);
            int idx = ((t >> 3) - (s >> 3) + 7) * 15 + (t & 7) - (s & 7) + 7;
            float val = sacc[ni][r] * 0.125f + Bs[idx];
            val = fminf(fmaxf(val, -50.0f), 50.0f);
            Ps[t * AST + s] = val;
        }
    }
    __syncthreads();

    // ---- softmax over s: 2 threads per row ----
    {
        int row = tid >> 1, hf = tid & 1;
        float* pr = Ps + row * AST + hf * 32;
        float mx = -1e30f;
        #pragma unroll
        for (int j = 0; j < 32; j++) mx = fmaxf(mx, pr[j]);
        mx = fmaxf(mx, __shfl_xor_sync(0xffffffffu, mx, 1));
        float sum = 0.0f;
        #pragma unroll
        for (int j = 0; j < 32; j++) { float e = __expf(pr[j] - mx); pr[j] = e; sum += e; }
        sum += __shfl_xor_sync(0xffffffffu, sum, 1);
        float inv = 1.0f / sum;
        unsigned* pu = reinterpret_cast<unsigned*>(pr);
        #pragma unroll
        for (int j = 0; j < 32; j++) pu[j] = f2tf(pr[j] * inv);
    }
    __syncthreads();

    // ---- ctx = P V ----
    const unsigned* Pu = reinterpret_cast<const unsigned*>(Ps);
    float cacc[8][4];
    #pragma unroll
    for (int i = 0; i < 8; i++)
        #pragma unroll
        for (int r = 0; r < 4; r++) cacc[i][r] = 0.0f;
    #pragma unroll
    for (int ks = 0; ks < 8; ks++) {
        const int k0 = ks * 8;
        unsigned a[4];
        a[0] = Pu[(w * 16 + gid) * AST + k0 + tig];
        a[1] = Pu[(w * 16 + gid + 8) * AST + k0 + tig];
        a[2] = Pu[(w * 16 + gid) * AST + k0 + tig + 4];
        a[3] = Pu[(w * 16 + gid + 8) * AST + k0 + tig + 4];
        #pragma unroll
        for (int ni = 0; ni < 8; ni++) {
            unsigned b0 = Vs[(k0 + tig) * VST + ni * 8 + gid];
            unsigned b1 = Vs[(k0 + tig + 4) * VST + ni * 8 + gid];
            mma8(cacc[ni], a, b0, b1);
        }
    }
    #pragma unroll
    for (int ni = 0; ni < 8; ni++) {
        int t0 = w * 16 + gid;
        int d0 = ni * 8 + tig * 2;
        *reinterpret_cast<float2*>(ctx + base + (size_t)t0 * DM + d0) =
            make_float2(cacc[ni][0], cacc[ni][1]);
        *reinterpret_cast<float2*>(ctx + base + (size_t)(t0 + 8) * DM + d0) =
            make_float2(cacc[ni][2], cacc[ni][3]);
    }
}

// ---------------- host orchestration ----------------
extern "C" void kernel_launch(void* const* d_in, const int* in_sizes, int n_in,
                              void* d_out, int out_size) {
    const float* x     = (const float*)d_in[0];
    const float* ln1w  = (const float*)d_in[1];
    const float* ln1b  = (const float*)d_in[2];
    const float* Wq    = (const float*)d_in[3];
    const float* bq    = (const float*)d_in[4];
    const float* Wk    = (const float*)d_in[5];
    const float* bk    = (const float*)d_in[6];
    const float* Wv    = (const float*)d_in[7];
    const float* bv    = (const float*)d_in[8];
    const float* Wo    = (const float*)d_in[9];
    const float* bo    = (const float*)d_in[10];
    const float* rel   = (const float*)d_in[11];
    const float* ln2w  = (const float*)d_in[12];
    const float* ln2b  = (const float*)d_in[13];
    const float* Wp    = (const float*)d_in[14];
    const float* bp    = (const float*)d_in[15];
    const float* Wf    = (const float*)d_in[16];
    const float* bf    = (const float*)d_in[17];

    float *h, *q, *k, *v, *c, *g;
    cudaGetSymbolAddress((void**)&h, g_h);
    cudaGetSymbolAddress((void**)&q, g_q);
    cudaGetSymbolAddress((void**)&k, g_k);
    cudaGetSymbolAddress((void**)&v, g_v);
    cudaGetSymbolAddress((void**)&c, g_c);
    cudaGetSymbolAddress((void**)&g, g_g);

    const int asmem = ASMEM_WORDS * 4;
    cudaFuncSetAttribute(attn_kernel, cudaFuncAttributeMaxDynamicSharedMemorySize, asmem);

    float* xb = (float*)d_out;  // fp32 residual stream lives in the output buffer
    cudaMemcpyAsync(xb, x, sizeof(float) * (size_t)MT * DM, cudaMemcpyDeviceToDevice);

    const dim3 gSq(DM / 128, MT / 128);     // (4, 256)
    const dim3 gGlu(DFFN / 64, MT / 128);   // (30, 256)
    const dim3 gAttn(HN, BN_);              // (8, 512)

    for (int l = 0; l < LNUM; l++) {
        const size_t lD  = (size_t)l * DM;
        const size_t lDD = (size_t)l * DM * DM;

        ln_kernel<<<MT, 128>>>(xb, ln1w + lD, ln1b + lD, h);
        gemm_tf32<0><<<gSq, 256>>>(h, Wq + lDD, bq + lD, q, DM, DM, DM);
        gemm_tf32<0><<<gSq, 256>>>(h, Wk + lDD, bk + lD, k, DM, DM, DM);
        gemm_tf32<0><<<gSq, 256>>>(h, Wv + lDD, bv + lD, v, DM, DM, DM);
        attn_kernel<<<gAttn, 128, asmem>>>(q, k, v, rel + (size_t)l * 225 * HN, c);
        gemm_tf32<1><<<gSq, 256>>>(c, Wo + lDD, bo + lD, xb, DM, DM, DM);

        ln_kernel<<<MT, 128>>>(xb, ln2w + lD, ln2b + lD, h);
        glu_gemm<<<gGlu, 256>>>(h, Wp + (size_t)l * DM * NN2, bp + (size_t)l * NN2, g);
        gemm_tf32<1><<<gSq, 256>>>(g, Wf + (size_t)l * DFFN * DM, bf + lD, xb,
                                   DM, DFFN, DFFN);
    }
}

// round 13
// speedup vs baseline: 1.2808x; 1.2808x over previous
#include <cuda_runtime.h>
#include <math.h>

// ---------------- problem constants ----------------
#define LNUM 13
#define DM   512
#define HN   8
#define DKN  64
#define DFFN 1920
#define NN2  (2*DFFN)
#define TN   64
#define BN_  512
#define MT   (BN_*TN)          // 32768 tokens

// ---------------- scratch (device globals; no allocs allowed) ----------------
__device__ float g_h[16777216];   // MT*DM   (post-LN activations)
__device__ float g_q[16777216];
__device__ float g_k[16777216];
__device__ float g_v[16777216];
__device__ float g_c[16777216];   // attention context
__device__ float g_g[62914560];   // MT*DFFN (gated FFN intermediate)

// ---------------- helpers ----------------
__device__ __forceinline__ unsigned f2tf(float x) {
    unsigned r; asm("cvt.rna.tf32.f32 %0, %1;" : "=r"(r) : "f"(x)); return r;
}
__device__ __forceinline__ uint4 cvt4(float4 v) {
    return make_uint4(f2tf(v.x), f2tf(v.y), f2tf(v.z), f2tf(v.w));
}
__device__ __forceinline__ void mma8(float c[4], const unsigned a[4],
                                     unsigned b0, unsigned b1) {
    asm volatile(
        "mma.sync.aligned.m16n8k8.row.col.f32.tf32.tf32.f32 "
        "{%0,%1,%2,%3}, {%4,%5,%6,%7}, {%8,%9}, {%0,%1,%2,%3};\n"
        : "+f"(c[0]), "+f"(c[1]), "+f"(c[2]), "+f"(c[3])
        : "r"(a[0]), "r"(a[1]), "r"(a[2]), "r"(a[3]), "r"(b0), "r"(b1));
}
__device__ __forceinline__ float gelu_exact(float x) {
    return 0.5f * x * (1.0f + erff(x * 0.70710678118654752f));
}
__device__ __forceinline__ void cp16(unsigned* smem, const float* gmem) {
    unsigned saddr = (unsigned)__cvta_generic_to_shared(smem);
    asm volatile("cp.async.cg.shared.global [%0], [%1], 16;\n"
                 :: "r"(saddr), "l"(gmem));
}
__device__ __forceinline__ void cp_commit() {
    asm volatile("cp.async.commit_group;\n");
}
template<int N> __device__ __forceinline__ void cp_wait() {
    asm volatile("cp.async.wait_group %0;\n" :: "n"(N));
}

// ---------------- LayerNorm: one block (128 thr) per token row of 512 ----------------
__global__ void ln_kernel(const float* __restrict__ x, const float* __restrict__ w,
                          const float* __restrict__ b, float* __restrict__ out) {
    const int row = blockIdx.x;
    const int tid = threadIdx.x;
    const float4 v = reinterpret_cast<const float4*>(x + (size_t)row * DM)[tid];
    float s  = v.x + v.y + v.z + v.w;
    float ss = v.x*v.x + v.y*v.y + v.z*v.z + v.w*v.w;
    #pragma unroll
    for (int o = 16; o > 0; o >>= 1) {
        s  += __shfl_xor_sync(0xffffffffu, s,  o);
        ss += __shfl_xor_sync(0xffffffffu, ss, o);
    }
    __shared__ float sh[8];
    const int wid = tid >> 5;
    if ((tid & 31) == 0) { sh[wid] = s; sh[4 + wid] = ss; }
    __syncthreads();
    s  = sh[0] + sh[1] + sh[2] + sh[3];
    ss = sh[4] + sh[5] + sh[6] + sh[7];
    const float mean = s * (1.0f / DM);
    const float var  = ss * (1.0f / DM) - mean * mean;
    const float inv  = rsqrtf(var + 1e-5f);
    const float4 wv = reinterpret_cast<const float4*>(w)[tid];
    const float4 bv = reinterpret_cast<const float4*>(b)[tid];
    float4 o;
    o.x = (v.x - mean) * inv * wv.x + bv.x;
    o.y = (v.y - mean) * inv * wv.y + bv.y;
    o.z = (v.z - mean) * inv * wv.z + bv.z;
    o.w = (v.w - mean) * inv * wv.w + bv.w;
    reinterpret_cast<float4*>(out + (size_t)row * DM)[tid] = o;
}

// ---------------- tf32 GEMM, 3-stage cp.async pipeline ----------------
// C = A(MxK,lda) @ W(KxN) + bias [+C]; tile 128x128x32, 256 threads.
// smem holds raw fp32; mma.tf32 truncates mantissa (error < 1e-3 budget).
#define GA_W  (128 * 36)            // A stage words, stride 36 (≡4 mod 32)
#define GW_W  (32 * 136)            // W stage words, stride 136 (≡8 mod 32)
#define GSTG  (GA_W + GW_W)         // 8960 words per stage
#define GSMEM (3 * GSTG * 4)        // 107520 bytes

template<int MODE>  // 0: overwrite, 1: residual accumulate into C
__global__ void __launch_bounds__(256, 2) gemm_tf32(
    const float* __restrict__ A, const float* __restrict__ W,
    const float* __restrict__ bias, float* __restrict__ C,
    int N, int K, int lda) {
    extern __shared__ unsigned sm[];
    const int tid  = threadIdx.x;
    const int m0   = blockIdx.y * 128;
    const int n0   = blockIdx.x * 128;
    const int w    = tid >> 5, lane = tid & 31, gid = lane >> 2, tig = lane & 3;
    const int wm   = (w & 1) * 64, wn = (w >> 1) * 32;

    // per-thread load coordinates
    const int a_mm[4] = { (tid + 0)   >> 3, (tid + 256) >> 3,
                          (tid + 512) >> 3, (tid + 768) >> 3 };
    const int a_k4   = (tid & 7) << 2;
    const int w_kk[4] = { (tid + 0)   >> 5, (tid + 256) >> 5,
                          (tid + 512) >> 5, (tid + 768) >> 5 };
    const int w_n4   = (tid & 31) << 2;

    auto load_stage = [&](int s, int kb) {
        unsigned* As = sm + s * GSTG;
        unsigned* Ws = As + GA_W;
        #pragma unroll
        for (int j = 0; j < 4; j++)
            cp16(&As[a_mm[j] * 36 + a_k4],
                 A + (size_t)(m0 + a_mm[j]) * lda + kb + a_k4);
        #pragma unroll
        for (int j = 0; j < 4; j++)
            cp16(&Ws[w_kk[j] * 136 + w_n4],
                 W + (size_t)(kb + w_kk[j]) * N + n0 + w_n4);
    };

    float acc[4][4][4];
    #pragma unroll
    for (int i = 0; i < 4; i++)
        #pragma unroll
        for (int j = 0; j < 4; j++)
            #pragma unroll
            for (int r = 0; r < 4; r++) acc[i][j][r] = 0.0f;

    const int nk = K >> 5;       // K/32, always >= 2 here
    load_stage(0, 0);  cp_commit();
    load_stage(1, 32); cp_commit();

    for (int it = 0; it < nk; it++) {
        cp_wait<1>();
        __syncthreads();
        const int nxt = it + 2;
        if (nxt < nk) load_stage(nxt % 3, nxt << 5);
        cp_commit();                       // commit (possibly empty) to keep counts aligned

        const unsigned* As = sm + (it % 3) * GSTG;
        const unsigned* Ws = As + GA_W;
        #pragma unroll
        for (int ks = 0; ks < 4; ks++) {
            const int k0 = ks * 8;
            unsigned a[4][4];
            #pragma unroll
            for (int mi = 0; mi < 4; mi++) {
                int r0 = wm + mi * 16 + gid;
                a[mi][0] = As[r0 * 36 + k0 + tig];
                a[mi][1] = As[(r0 + 8) * 36 + k0 + tig];
                a[mi][2] = As[r0 * 36 + k0 + tig + 4];
                a[mi][3] = As[(r0 + 8) * 36 + k0 + tig + 4];
            }
            #pragma unroll
            for (int ni = 0; ni < 4; ni++) {
                unsigned b0 = Ws[(k0 + tig) * 136 + wn + ni * 8 + gid];
                unsigned b1 = Ws[(k0 + tig + 4) * 136 + wn + ni * 8 + gid];
                #pragma unroll
                for (int mi = 0; mi < 4; mi++) mma8(acc[mi][ni], a[mi], b0, b1);
            }
        }
    }

    #pragma unroll
    for (int mi = 0; mi < 4; mi++) {
        #pragma unroll
        for (int ni = 0; ni < 4; ni++) {
            int row = m0 + wm + mi * 16 + gid;
            int col = n0 + wn + ni * 8 + tig * 2;
            float2 bv = *reinterpret_cast<const float2*>(bias + col);
            float* p0 = C + (size_t)row * N + col;
            float* p1 = C + (size_t)(row + 8) * N + col;
            float v0 = acc[mi][ni][0] + bv.x, v1 = acc[mi][ni][1] + bv.y;
            float v2 = acc[mi][ni][2] + bv.x, v3 = acc[mi][ni][3] + bv.y;
            if (MODE == 1) {
                float2 o0 = *reinterpret_cast<float2*>(p0);
                float2 o1 = *reinterpret_cast<float2*>(p1);
                v0 += o0.x; v1 += o0.y; v2 += o1.x; v3 += o1.y;
            }
            *reinterpret_cast<float2*>(p0) = make_float2(v0, v1);
            *reinterpret_cast<float2*>(p1) = make_float2(v2, v3);
        }
    }
}

// ---------------- fused dual-GEMM + GLU, 3-stage cp.async pipeline ----------------
// G = gelu(A@Wp[:, :DFF]+bp1) * (A@Wp[:, DFF:]+bp2); tile 128 x (64 per half) x 32
#define LW_W  (32 * 72)             // each half-W stage words, stride 72 (≡8 mod 32)
#define LSTG  (GA_W + 2 * LW_W)     // 9216 words per stage
#define LSMEM (3 * LSTG * 4)        // 110592 bytes

__global__ void __launch_bounds__(256, 2) glu_gemm(
    const float* __restrict__ A, const float* __restrict__ Wp,
    const float* __restrict__ bp, float* __restrict__ G) {
    extern __shared__ unsigned sm[];
    const int tid = threadIdx.x;
    const int m0  = blockIdx.y * 128;
    const int n0  = blockIdx.x * 64;
    const int w   = tid >> 5, lane = tid & 31, gid = lane >> 2, tig = lane & 3;
    const int wm  = (w & 1) * 64, wn = (w >> 1) * 16;

    const int a_mm[4] = { (tid + 0)   >> 3, (tid + 256) >> 3,
                          (tid + 512) >> 3, (tid + 768) >> 3 };
    const int a_k4   = (tid & 7) << 2;
    const int w_kk[2] = { (tid + 0) >> 4, (tid + 256) >> 4 };
    const int w_n4   = (tid & 15) << 2;

    auto load_stage = [&](int s, int kb) {
        unsigned* As = sm + s * LSTG;
        unsigned* W1 = As + GA_W;
        unsigned* W2 = W1 + LW_W;
        #pragma unroll
        for (int j = 0; j < 4; j++)
            cp16(&As[a_mm[j] * 36 + a_k4],
                 A + (size_t)(m0 + a_mm[j]) * DM + kb + a_k4);
        #pragma unroll
        for (int j = 0; j < 2; j++) {
            const float* wrow = Wp + (size_t)(kb + w_kk[j]) * NN2 + n0 + w_n4;
            cp16(&W1[w_kk[j] * 72 + w_n4], wrow);
            cp16(&W2[w_kk[j] * 72 + w_n4], wrow + DFFN);
        }
    };

    float ac1[4][2][4], ac2[4][2][4];
    #pragma unroll
    for (int i = 0; i < 4; i++)
        #pragma unroll
        for (int j = 0; j < 2; j++)
            #pragma unroll
            for (int r = 0; r < 4; r++) { ac1[i][j][r] = 0.0f; ac2[i][j][r] = 0.0f; }

    const int nk = DM >> 5;   // 16
    load_stage(0, 0);  cp_commit();
    load_stage(1, 32); cp_commit();

    for (int it = 0; it < nk; it++) {
        cp_wait<1>();
        __syncthreads();
        const int nxt = it + 2;
        if (nxt < nk) load_stage(nxt % 3, nxt << 5);
        cp_commit();

        const unsigned* As = sm + (it % 3) * LSTG;
        const unsigned* W1 = As + GA_W;
        const unsigned* W2 = W1 + LW_W;
        #pragma unroll
        for (int ks = 0; ks < 4; ks++) {
            const int k0 = ks * 8;
            unsigned a[4][4];
            #pragma unroll
            for (int mi = 0; mi < 4; mi++) {
                int r0 = wm + mi * 16 + gid;
                a[mi][0] = As[r0 * 36 + k0 + tig];
                a[mi][1] = As[(r0 + 8) * 36 + k0 + tig];
                a[mi][2] = As[r0 * 36 + k0 + tig + 4];
                a[mi][3] = As[(r0 + 8) * 36 + k0 + tig + 4];
            }
            #pragma unroll
            for (int ni = 0; ni < 2; ni++) {
                int cb = wn + ni * 8 + gid;
                unsigned b0 = W1[(k0 + tig) * 72 + cb];
                unsigned b1 = W1[(k0 + tig + 4) * 72 + cb];
                #pragma unroll
                for (int mi = 0; mi < 4; mi++) mma8(ac1[mi][ni], a[mi], b0, b1);
                unsigned c0 = W2[(k0 + tig) * 72 + cb];
                unsigned c1 = W2[(k0 + tig + 4) * 72 + cb];
                #pragma unroll
                for (int mi = 0; mi < 4; mi++) mma8(ac2[mi][ni], a[mi], c0, c1);
            }
        }
    }

    #pragma unroll
    for (int mi = 0; mi < 4; mi++) {
        #pragma unroll
        for (int ni = 0; ni < 2; ni++) {
            int row = m0 + wm + mi * 16 + gid;
            int col = n0 + wn + ni * 8 + tig * 2;
            float2 b1 = *reinterpret_cast<const float2*>(bp + col);
            float2 b2 = *reinterpret_cast<const float2*>(bp + DFFN + col);
            float g0 = gelu_exact(ac1[mi][ni][0] + b1.x) * (ac2[mi][ni][0] + b2.x);
            float g1 = gelu_exact(ac1[mi][ni][1] + b1.y) * (ac2[mi][ni][1] + b2.y);
            float g2 = gelu_exact(ac1[mi][ni][2] + b1.x) * (ac2[mi][ni][2] + b2.x);
            float g3 = gelu_exact(ac1[mi][ni][3] + b1.y) * (ac2[mi][ni][3] + b2.y);
            *reinterpret_cast<float2*>(G + (size_t)row * DFFN + col)       = make_float2(g0, g1);
            *reinterpret_cast<float2*>(G + (size_t)(row + 8) * DFFN + col) = make_float2(g2, g3);
        }
    }
}

// ---------------- fused attention: one CTA per (b, h) ----------------
#define AST 68   // Q/K/P smem row stride (≡4 mod 32)
#define VST 72   // V smem row stride (≡8 mod 32)
#define ASMEM_WORDS (64*AST*3 + 64*VST + 240)
__global__ void __launch_bounds__(128) attn_kernel(
    const float* __restrict__ q, const float* __restrict__ k,
    const float* __restrict__ v, const float* __restrict__ tab,
    float* __restrict__ ctx) {
    extern __shared__ float smf[];
    unsigned* Qs = reinterpret_cast<unsigned*>(smf);
    unsigned* Ks = Qs + 64 * AST;
    unsigned* Vs = Ks + 64 * AST;
    float*    Ps = reinterpret_cast<float*>(Vs + 64 * VST);
    float*    Bs = Ps + 64 * AST;

    const int hh = blockIdx.x, bb = blockIdx.y;
    const int tid = threadIdx.x;
    const size_t base = ((size_t)bb * TN) * DM + hh * DKN;

    #pragma unroll
    for (int i = 0; i < 8; i++) {
        int lin = tid + i * 128;
        int t = lin >> 4, d4 = (lin & 15) << 2;
        float4 vq = *reinterpret_cast<const float4*>(q + base + (size_t)t * DM + d4);
        float4 vk = *reinterpret_cast<const float4*>(k + base + (size_t)t * DM + d4);
        float4 vv = *reinterpret_cast<const float4*>(v + base + (size_t)t * DM + d4);
        *reinterpret_cast<uint4*>(&Qs[t * AST + d4]) = cvt4(vq);
        *reinterpret_cast<uint4*>(&Ks[t * AST + d4]) = cvt4(vk);
        *reinterpret_cast<uint4*>(&Vs[t * VST + d4]) = cvt4(vv);
    }
    for (int i = tid; i < 225; i += 128)
        Bs[i] = 2.0f * tanhf(tab[(size_t)i * HN + hh]);
    __syncthreads();

    const int w = tid >> 5, lane = tid & 31, gid = lane >> 2, tig = lane & 3;

    // ---- S = Q K^T ----
    float sacc[8][4];
    #pragma unroll
    for (int i = 0; i < 8; i++)
        #pragma unroll
        for (int r = 0; r < 4; r++) sacc[i][r] = 0.0f;
    #pragma unroll
    for (int ks = 0; ks < 8; ks++) {
        const int k0 = ks * 8;
        unsigned a[4];
        a[0] = Qs[(w * 16 + gid) * AST + k0 + tig];
        a[1] = Qs[(w * 16 + gid + 8) * AST + k0 + tig];
        a[2] = Qs[(w * 16 + gid) * AST + k0 + tig + 4];
        a[3] = Qs[(w * 16 + gid + 8) * AST + k0 + tig + 4];
        #pragma unroll
        for (int ni = 0; ni < 8; ni++) {
            unsigned b0 = Ks[(ni * 8 + gid) * AST + k0 + tig];
            unsigned b1 = Ks[(ni * 8 + gid) * AST + k0 + tig + 4];
            mma8(sacc[ni], a, b0, b1);
        }
    }
    #pragma unroll
    for (int ni = 0; ni < 8; ni++) {
        int t0 = w * 16 + gid;
        int s0 = ni * 8 + tig * 2;
        #pragma unroll
        for (int r = 0; r < 4; r++) {
            int t = t0 + (r >> 1) * 8;
            int s = s0 + (r & 1);
            int idx = ((t >> 3) - (s >> 3) + 7) * 15 + (t & 7) - (s & 7) + 7;
            float val = sacc[ni][r] * 0.125f + Bs[idx];
            val = fminf(fmaxf(val, -50.0f), 50.0f);
            Ps[t * AST + s] = val;
        }
    }
    __syncthreads();

    // ---- softmax over s: 2 threads per row ----
    {
        int row = tid >> 1, hf = tid & 1;
        float* pr = Ps + row * AST + hf * 32;
        float mx = -1e30f;
        #pragma unroll
        for (int j = 0; j < 32; j++) mx = fmaxf(mx, pr[j]);
        mx = fmaxf(mx, __shfl_xor_sync(0xffffffffu, mx, 1));
        float sum = 0.0f;
        #pragma unroll
        for (int j = 0; j < 32; j++) { float e = __expf(pr[j] - mx); pr[j] = e; sum += e; }
        sum += __shfl_xor_sync(0xffffffffu, sum, 1);
        float inv = 1.0f / sum;
        unsigned* pu = reinterpret_cast<unsigned*>(pr);
        #pragma unroll
        for (int j = 0; j < 32; j++) pu[j] = f2tf(pr[j] * inv);
    }
    __syncthreads();

    // ---- ctx = P V ----
    const unsigned* Pu = reinterpret_cast<const unsigned*>(Ps);
    float cacc[8][4];
    #pragma unroll
    for (int i = 0; i < 8; i++)
        #pragma unroll
        for (int r = 0; r < 4; r++) cacc[i][r] = 0.0f;
    #pragma unroll
    for (int ks = 0; ks < 8; ks++) {
        const int k0 = ks * 8;
        unsigned a[4];
        a[0] = Pu[(w * 16 + gid) * AST + k0 + tig];
        a[1] = Pu[(w * 16 + gid + 8) * AST + k0 + tig];
        a[2] = Pu[(w * 16 + gid) * AST + k0 + tig + 4];
        a[3] = Pu[(w * 16 + gid + 8) * AST + k0 + tig + 4];
        #pragma unroll
        for (int ni = 0; ni < 8; ni++) {
            unsigned b0 = Vs[(k0 + tig) * VST + ni * 8 + gid];
            unsigned b1 = Vs[(k0 + tig + 4) * VST + ni * 8 + gid];
            mma8(cacc[ni], a, b0, b1);
        }
    }
    #pragma unroll
    for (int ni = 0; ni < 8; ni++) {
        int t0 = w * 16 + gid;
        int d0 = ni * 8 + tig * 2;
        *reinterpret_cast<float2*>(ctx + base + (size_t)t0 * DM + d0) =
            make_float2(cacc[ni][0], cacc[ni][1]);
        *reinterpret_cast<float2*>(ctx + base + (size_t)(t0 + 8) * DM + d0) =
            make_float2(cacc[ni][2], cacc[ni][3]);
    }
}

// ---------------- host orchestration ----------------
extern "C" void kernel_launch(void* const* d_in, const int* in_sizes, int n_in,
                              void* d_out, int out_size) {
    const float* x     = (const float*)d_in[0];
    const float* ln1w  = (const float*)d_in[1];
    const float* ln1b  = (const float*)d_in[2];
    const float* Wq    = (const float*)d_in[3];
    const float* bq    = (const float*)d_in[4];
    const float* Wk    = (const float*)d_in[5];
    const float* bk    = (const float*)d_in[6];
    const float* Wv    = (const float*)d_in[7];
    const float* bv    = (const float*)d_in[8];
    const float* Wo    = (const float*)d_in[9];
    const float* bo    = (const float*)d_in[10];
    const float* rel   = (const float*)d_in[11];
    const float* ln2w  = (const float*)d_in[12];
    const float* ln2b  = (const float*)d_in[13];
    const float* Wp    = (const float*)d_in[14];
    const float* bp    = (const float*)d_in[15];
    const float* Wf    = (const float*)d_in[16];
    const float* bf    = (const float*)d_in[17];

    float *h, *q, *k, *v, *c, *g;
    cudaGetSymbolAddress((void**)&h, g_h);
    cudaGetSymbolAddress((void**)&q, g_q);
    cudaGetSymbolAddress((void**)&k, g_k);
    cudaGetSymbolAddress((void**)&v, g_v);
    cudaGetSymbolAddress((void**)&c, g_c);
    cudaGetSymbolAddress((void**)&g, g_g);

    const int asmem = ASMEM_WORDS * 4;
    cudaFuncSetAttribute(attn_kernel, cudaFuncAttributeMaxDynamicSharedMemorySize, asmem);
    cudaFuncSetAttribute(gemm_tf32<0>, cudaFuncAttributeMaxDynamicSharedMemorySize, GSMEM);
    cudaFuncSetAttribute(gemm_tf32<1>, cudaFuncAttributeMaxDynamicSharedMemorySize, GSMEM);
    cudaFuncSetAttribute(glu_gemm,     cudaFuncAttributeMaxDynamicSharedMemorySize, LSMEM);

    float* xb = (float*)d_out;  // fp32 residual stream lives in the output buffer
    cudaMemcpyAsync(xb, x, sizeof(float) * (size_t)MT * DM, cudaMemcpyDeviceToDevice);

    const dim3 gSq(DM / 128, MT / 128);     // (4, 256)
    const dim3 gGlu(DFFN / 64, MT / 128);   // (30, 256)
    const dim3 gAttn(HN, BN_);              // (8, 512)

    for (int l = 0; l < LNUM; l++) {
        const size_t lD  = (size_t)l * DM;
        const size_t lDD = (size_t)l * DM * DM;

        ln_kernel<<<MT, 128>>>(xb, ln1w + lD, ln1b + lD, h);
        gemm_tf32<0><<<gSq, 256, GSMEM>>>(h, Wq + lDD, bq + lD, q, DM, DM, DM);
        gemm_tf32<0><<<gSq, 256, GSMEM>>>(h, Wk + lDD, bk + lD, k, DM, DM, DM);
        gemm_tf32<0><<<gSq, 256, GSMEM>>>(h, Wv + lDD, bv + lD, v, DM, DM, DM);
        attn_kernel<<<gAttn, 128, asmem>>>(q, k, v, rel + (size_t)l * 225 * HN, c);
        gemm_tf32<1><<<gSq, 256, GSMEM>>>(c, Wo + lDD, bo + lD, xb, DM, DM, DM);

        ln_kernel<<<MT, 128>>>(xb, ln2w + lD, ln2b + lD, h);
        glu_gemm<<<gGlu, 256, LSMEM>>>(h, Wp + (size_t)l * DM * NN2, bp + (size_t)l * NN2, g);
        gemm_tf32<1><<<gSq, 256, GSMEM>>>(g, Wf + (size_t)l * DFFN * DM, bf + lD, xb,
                                          DM, DFFN, DFFN);
    }
}

// round 14
// speedup vs baseline: 1.2855x; 1.0037x over previous
#include <cuda_runtime.h>
#include <math.h>

// ---------------- problem constants ----------------
#define LNUM 13
#define DM   512
#define HN   8
#define DKN  64
#define DFFN 1920
#define NN2  (2*DFFN)
#define TN   64
#define BN_  512
#define MT   (BN_*TN)          // 32768 tokens

// ---------------- scratch (device globals; no allocs allowed) ----------------
__device__ float g_h[16777216];   // MT*DM   (post-LN activations)
__device__ float g_q[16777216];
__device__ float g_k[16777216];
__device__ float g_v[16777216];
__device__ float g_c[16777216];   // attention context
__device__ float g_g[62914560];   // MT*DFFN (gated FFN intermediate)

// ---------------- helpers ----------------
__device__ __forceinline__ unsigned f2tf(float x) {
    unsigned r; asm("cvt.rna.tf32.f32 %0, %1;" : "=r"(r) : "f"(x)); return r;
}
__device__ __forceinline__ uint4 cvt4(float4 v) {
    return make_uint4(f2tf(v.x), f2tf(v.y), f2tf(v.z), f2tf(v.w));
}
__device__ __forceinline__ void mma8(float c[4], const unsigned a[4],
                                     unsigned b0, unsigned b1) {
    asm volatile(
        "mma.sync.aligned.m16n8k8.row.col.f32.tf32.tf32.f32 "
        "{%0,%1,%2,%3}, {%4,%5,%6,%7}, {%8,%9}, {%0,%1,%2,%3};\n"
        : "+f"(c[0]), "+f"(c[1]), "+f"(c[2]), "+f"(c[3])
        : "r"(a[0]), "r"(a[1]), "r"(a[2]), "r"(a[3]), "r"(b0), "r"(b1));
}
__device__ __forceinline__ float gelu_exact(float x) {
    return 0.5f * x * (1.0f + erff(x * 0.70710678118654752f));
}
__device__ __forceinline__ void cp16(unsigned* smem, const float* gmem) {
    unsigned saddr = (unsigned)__cvta_generic_to_shared(smem);
    asm volatile("cp.async.cg.shared.global [%0], [%1], 16;\n"
                 :: "r"(saddr), "l"(gmem));
}
__device__ __forceinline__ void cp_commit() {
    asm volatile("cp.async.commit_group;\n");
}
template<int N> __device__ __forceinline__ void cp_wait() {
    asm volatile("cp.async.wait_group %0;\n" :: "n"(N));
}

// ---------------- LayerNorm: one block (128 thr) per token row of 512 ----------------
__global__ void ln_kernel(const float* __restrict__ x, const float* __restrict__ w,
                          const float* __restrict__ b, float* __restrict__ out) {
    const int row = blockIdx.x;
    const int tid = threadIdx.x;
    const float4 v = reinterpret_cast<const float4*>(x + (size_t)row * DM)[tid];
    float s  = v.x + v.y + v.z + v.w;
    float ss = v.x*v.x + v.y*v.y + v.z*v.z + v.w*v.w;
    #pragma unroll
    for (int o = 16; o > 0; o >>= 1) {
        s  += __shfl_xor_sync(0xffffffffu, s,  o);
        ss += __shfl_xor_sync(0xffffffffu, ss, o);
    }
    __shared__ float sh[8];
    const int wid = tid >> 5;
    if ((tid & 31) == 0) { sh[wid] = s; sh[4 + wid] = ss; }
    __syncthreads();
    s  = sh[0] + sh[1] + sh[2] + sh[3];
    ss = sh[4] + sh[5] + sh[6] + sh[7];
    const float mean = s * (1.0f / DM);
    const float var  = ss * (1.0f / DM) - mean * mean;
    const float inv  = rsqrtf(var + 1e-5f);
    const float4 wv = reinterpret_cast<const float4*>(w)[tid];
    const float4 bv = reinterpret_cast<const float4*>(b)[tid];
    float4 o;
    o.x = (v.x - mean) * inv * wv.x + bv.x;
    o.y = (v.y - mean) * inv * wv.y + bv.y;
    o.z = (v.z - mean) * inv * wv.z + bv.z;
    o.w = (v.w - mean) * inv * wv.w + bv.w;
    reinterpret_cast<float4*>(out + (size_t)row * DM)[tid] = o;
}

// ---------------- tf32 GEMM, 3-stage cp.async pipeline ----------------
// C = A(MxK,lda) @ W(KxN) + bias [+C]; tile 128x128x32, 256 threads.
// smem holds raw fp32; mma.tf32 truncates mantissa (error < 1e-3 budget).
#define GA_W  (128 * 36)            // A stage words, stride 36 (≡4 mod 32)
#define GW_W  (32 * 136)            // W stage words, stride 136 (≡8 mod 32)
#define GSTG  (GA_W + GW_W)         // 8960 words per stage
#define GSMEM (3 * GSTG * 4)        // 107520 bytes

template<int MODE>  // 0: overwrite, 1: residual accumulate into C
__global__ void __launch_bounds__(256, 2) gemm_tf32(
    const float* __restrict__ A, const float* __restrict__ W,
    const float* __restrict__ bias, float* __restrict__ C,
    int N, int K, int lda) {
    extern __shared__ unsigned sm[];
    const int tid  = threadIdx.x;
    const int m0   = blockIdx.y * 128;
    const int n0   = blockIdx.x * 128;
    const int w    = tid >> 5, lane = tid & 31, gid = lane >> 2, tig = lane & 3;
    const int wm   = (w & 1) * 64, wn = (w >> 1) * 32;

    // per-thread load coordinates
    const int a_mm[4] = { (tid + 0)   >> 3, (tid + 256) >> 3,
                          (tid + 512) >> 3, (tid + 768) >> 3 };
    const int a_k4   = (tid & 7) << 2;
    const int w_kk[4] = { (tid + 0)   >> 5, (tid + 256) >> 5,
                          (tid + 512) >> 5, (tid + 768) >> 5 };
    const int w_n4   = (tid & 31) << 2;

    auto load_stage = [&](int s, int kb) {
        unsigned* As = sm + s * GSTG;
        unsigned* Ws = As + GA_W;
        #pragma unroll
        for (int j = 0; j < 4; j++)
            cp16(&As[a_mm[j] * 36 + a_k4],
                 A + (size_t)(m0 + a_mm[j]) * lda + kb + a_k4);
        #pragma unroll
        for (int j = 0; j < 4; j++)
            cp16(&Ws[w_kk[j] * 136 + w_n4],
                 W + (size_t)(kb + w_kk[j]) * N + n0 + w_n4);
    };

    float acc[4][4][4];
    #pragma unroll
    for (int i = 0; i < 4; i++)
        #pragma unroll
        for (int j = 0; j < 4; j++)
            #pragma unroll
            for (int r = 0; r < 4; r++) acc[i][j][r] = 0.0f;

    const int nk = K >> 5;       // K/32, always >= 2 here
    load_stage(0, 0);  cp_commit();
    load_stage(1, 32); cp_commit();

    for (int it = 0; it < nk; it++) {
        cp_wait<1>();
        __syncthreads();
        const int nxt = it + 2;
        if (nxt < nk) load_stage(nxt % 3, nxt << 5);
        cp_commit();                       // commit (possibly empty) to keep counts aligned

        const unsigned* As = sm + (it % 3) * GSTG;
        const unsigned* Ws = As + GA_W;
        #pragma unroll
        for (int ks = 0; ks < 4; ks++) {
            const int k0 = ks * 8;
            unsigned a[4][4];
            #pragma unroll
            for (int mi = 0; mi < 4; mi++) {
                int r0 = wm + mi * 16 + gid;
                a[mi][0] = As[r0 * 36 + k0 + tig];
                a[mi][1] = As[(r0 + 8) * 36 + k0 + tig];
                a[mi][2] = As[r0 * 36 + k0 + tig + 4];
                a[mi][3] = As[(r0 + 8) * 36 + k0 + tig + 4];
            }
            #pragma unroll
            for (int ni = 0; ni < 4; ni++) {
                unsigned b0 = Ws[(k0 + tig) * 136 + wn + ni * 8 + gid];
                unsigned b1 = Ws[(k0 + tig + 4) * 136 + wn + ni * 8 + gid];
                #pragma unroll
                for (int mi = 0; mi < 4; mi++) mma8(acc[mi][ni], a[mi], b0, b1);
            }
        }
    }

    #pragma unroll
    for (int mi = 0; mi < 4; mi++) {
        #pragma unroll
        for (int ni = 0; ni < 4; ni++) {
            int row = m0 + wm + mi * 16 + gid;
            int col = n0 + wn + ni * 8 + tig * 2;
            float2 bv = *reinterpret_cast<const float2*>(bias + col);
            float* p0 = C + (size_t)row * N + col;
            float* p1 = C + (size_t)(row + 8) * N + col;
            float v0 = acc[mi][ni][0] + bv.x, v1 = acc[mi][ni][1] + bv.y;
            float v2 = acc[mi][ni][2] + bv.x, v3 = acc[mi][ni][3] + bv.y;
            if (MODE == 1) {
                float2 o0 = *reinterpret_cast<float2*>(p0);
                float2 o1 = *reinterpret_cast<float2*>(p1);
                v0 += o0.x; v1 += o0.y; v2 += o1.x; v3 += o1.y;
            }
            *reinterpret_cast<float2*>(p0) = make_float2(v0, v1);
            *reinterpret_cast<float2*>(p1) = make_float2(v2, v3);
        }
    }
}

// ---------------- fused dual-GEMM + GLU, 3-stage cp.async pipeline ----------------
// G = gelu(A@Wp[:, :DFF]+bp1) * (A@Wp[:, DFF:]+bp2); tile 128 x (64 per half) x 32
#define LW_W  (32 * 72)             // each half-W stage words, stride 72 (≡8 mod 32)
#define LSTG  (GA_W + 2 * LW_W)     // 9216 words per stage
#define LSMEM (3 * LSTG * 4)        // 110592 bytes

__global__ void __launch_bounds__(256, 2) glu_gemm(
    const float* __restrict__ A, const float* __restrict__ Wp,
    const float* __restrict__ bp, float* __restrict__ G) {
    extern __shared__ unsigned sm[];
    const int tid = threadIdx.x;
    const int m0  = blockIdx.y * 128;
    const int n0  = blockIdx.x * 64;
    const int w   = tid >> 5, lane = tid & 31, gid = lane >> 2, tig = lane & 3;
    const int wm  = (w & 1) * 64, wn = (w >> 1) * 16;

    const int a_mm[4] = { (tid + 0)   >> 3, (tid + 256) >> 3,
                          (tid + 512) >> 3, (tid + 768) >> 3 };
    const int a_k4   = (tid & 7) << 2;
    const int w_kk[2] = { (tid + 0) >> 4, (tid + 256) >> 4 };
    const int w_n4   = (tid & 15) << 2;

    auto load_stage = [&](int s, int kb) {
        unsigned* As = sm + s * LSTG;
        unsigned* W1 = As + GA_W;
        unsigned* W2 = W1 + LW_W;
        #pragma unroll
        for (int j = 0; j < 4; j++)
            cp16(&As[a_mm[j] * 36 + a_k4],
                 A + (size_t)(m0 + a_mm[j]) * DM + kb + a_k4);
        #pragma unroll
        for (int j = 0; j < 2; j++) {
            const float* wrow = Wp + (size_t)(kb + w_kk[j]) * NN2 + n0 + w_n4;
            cp16(&W1[w_kk[j] * 72 + w_n4], wrow);
            cp16(&W2[w_kk[j] * 72 + w_n4], wrow + DFFN);
        }
    };

    float ac1[4][2][4], ac2[4][2][4];
    #pragma unroll
    for (int i = 0; i < 4; i++)
        #pragma unroll
        for (int j = 0; j < 2; j++)
            #pragma unroll
            for (int r = 0; r < 4; r++) { ac1[i][j][r] = 0.0f; ac2[i][j][r] = 0.0f; }

    const int nk = DM >> 5;   // 16
    load_stage(0, 0);  cp_commit();
    load_stage(1, 32); cp_commit();

    for (int it = 0; it < nk; it++) {
        cp_wait<1>();
        __syncthreads();
        const int nxt = it + 2;
        if (nxt < nk) load_stage(nxt % 3, nxt << 5);
        cp_commit();

        const unsigned* As = sm + (it % 3) * LSTG;
        const unsigned* W1 = As + GA_W;
        const unsigned* W2 = W1 + LW_W;
        #pragma unroll
        for (int ks = 0; ks < 4; ks++) {
            const int k0 = ks * 8;
            unsigned a[4][4];
            #pragma unroll
            for (int mi = 0; mi < 4; mi++) {
                int r0 = wm + mi * 16 + gid;
                a[mi][0] = As[r0 * 36 + k0 + tig];
                a[mi][1] = As[(r0 + 8) * 36 + k0 + tig];
                a[mi][2] = As[r0 * 36 + k0 + tig + 4];
                a[mi][3] = As[(r0 + 8) * 36 + k0 + tig + 4];
            }
            #pragma unroll
            for (int ni = 0; ni < 2; ni++) {
                int cb = wn + ni * 8 + gid;
                unsigned b0 = W1[(k0 + tig) * 72 + cb];
                unsigned b1 = W1[(k0 + tig + 4) * 72 + cb];
                #pragma unroll
                for (int mi = 0; mi < 4; mi++) mma8(ac1[mi][ni], a[mi], b0, b1);
                unsigned c0 = W2[(k0 + tig) * 72 + cb];
                unsigned c1 = W2[(k0 + tig + 4) * 72 + cb];
                #pragma unroll
                for (int mi = 0; mi < 4; mi++) mma8(ac2[mi][ni], a[mi], c0, c1);
            }
        }
    }

    #pragma unroll
    for (int mi = 0; mi < 4; mi++) {
        #pragma unroll
        for (int ni = 0; ni < 2; ni++) {
            int row = m0 + wm + mi * 16 + gid;
            int col = n0 + wn + ni * 8 + tig * 2;
            float2 b1 = *reinterpret_cast<const float2*>(bp + col);
            float2 b2 = *reinterpret_cast<const float2*>(bp + DFFN + col);
            float g0 = gelu_exact(ac1[mi][ni][0] + b1.x) * (ac2[mi][ni][0] + b2.x);
            float g1 = gelu_exact(ac1[mi][ni][1] + b1.y) * (ac2[mi][ni][1] + b2.y);
            float g2 = gelu_exact(ac1[mi][ni][2] + b1.x) * (ac2[mi][ni][2] + b2.x);
            float g3 = gelu_exact(ac1[mi][ni][3] + b1.y) * (ac2[mi][ni][3] + b2.y);
            *reinterpret_cast<float2*>(G + (size_t)row * DFFN + col)       = make_float2(g0, g1);
            *reinterpret_cast<float2*>(G + (size_t)(row + 8) * DFFN + col) = make_float2(g2, g3);
        }
    }
}

// ---------------- fused attention: one CTA per (b, h) ----------------
#define AST 68   // Q/K/P smem row stride (≡4 mod 32)
#define VST 72   // V smem row stride (≡8 mod 32)
#define ASMEM_WORDS (64*AST*3 + 64*VST + 240)
__global__ void __launch_bounds__(128) attn_kernel(
    const float* __restrict__ q, const float* __restrict__ k,
    const float* __restrict__ v, const float* __restrict__ tab,
    float* __restrict__ ctx) {
    extern __shared__ float smf[];
    unsigned* Qs = reinterpret_cast<unsigned*>(smf);
    unsigned* Ks = Qs + 64 * AST;
    unsigned* Vs = Ks + 64 * AST;
    float*    Ps = reinterpret_cast<float*>(Vs + 64 * VST);
    float*    Bs = Ps + 64 * AST;

    const int hh = blockIdx.x, bb = blockIdx.y;
    const int tid = threadIdx.x;
    const size_t base = ((size_t)bb * TN) * DM + hh * DKN;

    #pragma unroll
    for (int i = 0; i < 8; i++) {
        int lin = tid + i * 128;
        int t = lin >> 4, d4 = (lin & 15) << 2;
        float4 vq = *reinterpret_cast<const float4*>(q + base + (size_t)t * DM + d4);
        float4 vk = *reinterpret_cast<const float4*>(k + base + (size_t)t * DM + d4);
        float4 vv = *reinterpret_cast<const float4*>(v + base + (size_t)t * DM + d4);
        *reinterpret_cast<uint4*>(&Qs[t * AST + d4]) = cvt4(vq);
        *reinterpret_cast<uint4*>(&Ks[t * AST + d4]) = cvt4(vk);
        *reinterpret_cast<uint4*>(&Vs[t * VST + d4]) = cvt4(vv);
    }
    for (int i = tid; i < 225; i += 128)
        Bs[i] = 2.0f * tanhf(tab[(size_t)i * HN + hh]);
    __syncthreads();

    const int w = tid >> 5, lane = tid & 31, gid = lane >> 2, tig = lane & 3;

    // ---- S = Q K^T ----
    float sacc[8][4];
    #pragma unroll
    for (int i = 0; i < 8; i++)
        #pragma unroll
        for (int r = 0; r < 4; r++) sacc[i][r] = 0.0f;
    #pragma unroll
    for (int ks = 0; ks < 8; ks++) {
        const int k0 = ks * 8;
        unsigned a[4];
        a[0] = Qs[(w * 16 + gid) * AST + k0 + tig];
        a[1] = Qs[(w * 16 + gid + 8) * AST + k0 + tig];
        a[2] = Qs[(w * 16 + gid) * AST + k0 + tig + 4];
        a[3] = Qs[(w * 16 + gid + 8) * AST + k0 + tig + 4];
        #pragma unroll
        for (int ni = 0; ni < 8; ni++) {
            unsigned b0 = Ks[(ni * 8 + gid) * AST + k0 + tig];
            unsigned b1 = Ks[(ni * 8 + gid) * AST + k0 + tig + 4];
            mma8(sacc[ni], a, b0, b1);
        }
    }
    #pragma unroll
    for (int ni = 0; ni < 8; ni++) {
        int t0 = w * 16 + gid;
        int s0 = ni * 8 + tig * 2;
        #pragma unroll
        for (int r = 0; r < 4; r++) {
            int t = t0 + (r >> 1) * 8;
            int s = s0 + (r & 1);
            int idx = ((t >> 3) - (s >> 3) + 7) * 15 + (t & 7) - (s & 7) + 7;
            float val = sacc[ni][r] * 0.125f + Bs[idx];
            val = fminf(fmaxf(val, -50.0f), 50.0f);
            Ps[t * AST + s] = val;
        }
    }
    __syncthreads();

    // ---- softmax over s: 2 threads per row ----
    {
        int row = tid >> 1, hf = tid & 1;
        float* pr = Ps + row * AST + hf * 32;
        float mx = -1e30f;
        #pragma unroll
        for (int j = 0; j < 32; j++) mx = fmaxf(mx, pr[j]);
        mx = fmaxf(mx, __shfl_xor_sync(0xffffffffu, mx, 1));
        float sum = 0.0f;
        #pragma unroll
        for (int j = 0; j < 32; j++) { float e = __expf(pr[j] - mx); pr[j] = e; sum += e; }
        sum += __shfl_xor_sync(0xffffffffu, sum, 1);
        float inv = 1.0f / sum;
        unsigned* pu = reinterpret_cast<unsigned*>(pr);
        #pragma unroll
        for (int j = 0; j < 32; j++) pu[j] = f2tf(pr[j] * inv);
    }
    __syncthreads();

    // ---- ctx = P V ----
    const unsigned* Pu = reinterpret_cast<const unsigned*>(Ps);
    float cacc[8][4];
    #pragma unroll
    for (int i = 0; i < 8; i++)
        #pragma unroll
        for (int r = 0; r < 4; r++) cacc[i][r] = 0.0f;
    #pragma unroll
    for (int ks = 0; ks < 8; ks++) {
        const int k0 = ks * 8;
        unsigned a[4];
        a[0] = Pu[(w * 16 + gid) * AST + k0 + tig];
        a[1] = Pu[(w * 16 + gid + 8) * AST + k0 + tig];
        a[2] = Pu[(w * 16 + gid) * AST + k0 + tig + 4];
        a[3] = Pu[(w * 16 + gid + 8) * AST + k0 + tig + 4];
        #pragma unroll
        for (int ni = 0; ni < 8; ni++) {
            unsigned b0 = Vs[(k0 + tig) * VST + ni * 8 + gid];
            unsigned b1 = Vs[(k0 + tig + 4) * VST + ni * 8 + gid];
            mma8(cacc[ni], a, b0, b1);
        }
    }
    #pragma unroll
    for (int ni = 0; ni < 8; ni++) {
        int t0 = w * 16 + gid;
        int d0 = ni * 8 + tig * 2;
        *reinterpret_cast<float2*>(ctx + base + (size_t)t0 * DM + d0) =
            make_float2(cacc[ni][0], cacc[ni][1]);
        *reinterpret_cast<float2*>(ctx + base + (size_t)(t0 + 8) * DM + d0) =
            make_float2(cacc[ni][2], cacc[ni][3]);
    }
}

// ---------------- host orchestration ----------------
extern "C" void kernel_launch(void* const* d_in, const int* in_sizes, int n_in,
                              void* d_out, int out_size) {
    const float* x     = (const float*)d_in[0];
    const float* ln1w  = (const float*)d_in[1];
    const float* ln1b  = (const float*)d_in[2];
    const float* Wq    = (const float*)d_in[3];
    const float* bq    = (const float*)d_in[4];
    const float* Wk    = (const float*)d_in[5];
    const float* bk    = (const float*)d_in[6];
    const float* Wv    = (const float*)d_in[7];
    const float* bv    = (const float*)d_in[8];
    const float* Wo    = (const float*)d_in[9];
    const float* bo    = (const float*)d_in[10];
    const float* rel   = (const float*)d_in[11];
    const float* ln2w  = (const float*)d_in[12];
    const float* ln2b  = (const float*)d_in[13];
    const float* Wp    = (const float*)d_in[14];
    const float* bp    = (const float*)d_in[15];
    const float* Wf    = (const float*)d_in[16];
    const float* bf    = (const float*)d_in[17];

    float *h, *q, *k, *v, *c, *g;
    cudaGetSymbolAddress((void**)&h, g_h);
    cudaGetSymbolAddress((void**)&q, g_q);
    cudaGetSymbolAddress((void**)&k, g_k);
    cudaGetSymbolAddress((void**)&v, g_v);
    cudaGetSymbolAddress((void**)&c, g_c);
    cudaGetSymbolAddress((void**)&g, g_g);

    const int asmem = ASMEM_WORDS * 4;
    cudaFuncSetAttribute(attn_kernel, cudaFuncAttributeMaxDynamicSharedMemorySize, asmem);
    cudaFuncSetAttribute(gemm_tf32<0>, cudaFuncAttributeMaxDynamicSharedMemorySize, GSMEM);
    cudaFuncSetAttribute(gemm_tf32<1>, cudaFuncAttributeMaxDynamicSharedMemorySize, GSMEM);
    cudaFuncSetAttribute(glu_gemm,     cudaFuncAttributeMaxDynamicSharedMemorySize, LSMEM);

    float* xb = (float*)d_out;  // fp32 residual stream lives in the output buffer
    cudaMemcpyAsync(xb, x, sizeof(float) * (size_t)MT * DM, cudaMemcpyDeviceToDevice);

    const dim3 gSq(DM / 128, MT / 128);     // (4, 256)
    const dim3 gGlu(DFFN / 64, MT / 128);   // (30, 256)
    const dim3 gAttn(HN, BN_);              // (8, 512)

    for (int l = 0; l < LNUM; l++) {
        const size_t lD  = (size_t)l * DM;
        const size_t lDD = (size_t)l * DM * DM;

        ln_kernel<<<MT, 128>>>(xb, ln1w + lD, ln1b + lD, h);
        gemm_tf32<0><<<gSq, 256, GSMEM>>>(h, Wq + lDD, bq + lD, q, DM, DM, DM);
        gemm_tf32<0><<<gSq, 256, GSMEM>>>(h, Wk + lDD, bk + lD, k, DM, DM, DM);
        gemm_tf32<0><<<gSq, 256, GSMEM>>>(h, Wv + lDD, bv + lD, v, DM, DM, DM);
        attn_kernel<<<gAttn, 128, asmem>>>(q, k, v, rel + (size_t)l * 225 * HN, c);
        gemm_tf32<1><<<gSq, 256, GSMEM>>>(c, Wo + lDD, bo + lD, xb, DM, DM, DM);

        ln_kernel<<<MT, 128>>>(xb, ln2w + lD, ln2b + lD, h);
        glu_gemm<<<gGlu, 256, LSMEM>>>(h, Wp + (size_t)l * DM * NN2, bp + (size_t)l * NN2, g);
        gemm_tf32<1><<<gSq, 256, GSMEM>>>(g, Wf + (size_t)l * DFFN * DM, bf + lD, xb,
                                          DM, DFFN, DFFN);
    }
}

// round 15
// speedup vs baseline: 1.2996x; 1.0109x over previous
#include <cuda_runtime.h>
#include <math.h>

// ---------------- problem constants ----------------
#define LNUM 13
#define DM   512
#define HN   8
#define DKN  64
#define DFFN 1920
#define NN2  (2*DFFN)
#define TN   64
#define BN_  512
#define MT   (BN_*TN)          // 32768 tokens

// ---------------- scratch (device globals; no allocs allowed) ----------------
__device__ float g_h[16777216];   // MT*DM   (post-LN activations, tf32-rounded)
__device__ float g_q[16777216];
__device__ float g_k[16777216];
__device__ float g_v[16777216];
__device__ float g_c[16777216];   // attention context (tf32-rounded)
__device__ float g_g[62914560];   // MT*DFFN (gated FFN intermediate, tf32-rounded)
// pre-rounded weights (tf32-representable fp32)
__device__ float g_wq[3407872];
__device__ float g_wk[3407872];
__device__ float g_wv[3407872];
__device__ float g_wo[3407872];
__device__ float g_wp[25559040];
__device__ float g_wf[12779520];

// ---------------- helpers ----------------
__device__ __forceinline__ unsigned f2tf(float x) {
    unsigned r; asm("cvt.rna.tf32.f32 %0, %1;" : "=r"(r) : "f"(x)); return r;
}
__device__ __forceinline__ float rndf(float x) { return __uint_as_float(f2tf(x)); }
__device__ __forceinline__ uint4 cvt4(float4 v) {
    return make_uint4(f2tf(v.x), f2tf(v.y), f2tf(v.z), f2tf(v.w));
}
__device__ __forceinline__ void mma8(float c[4], const unsigned a[4],
                                     unsigned b0, unsigned b1) {
    asm volatile(
        "mma.sync.aligned.m16n8k8.row.col.f32.tf32.tf32.f32 "
        "{%0,%1,%2,%3}, {%4,%5,%6,%7}, {%8,%9}, {%0,%1,%2,%3};\n"
        : "+f"(c[0]), "+f"(c[1]), "+f"(c[2]), "+f"(c[3])
        : "r"(a[0]), "r"(a[1]), "r"(a[2]), "r"(a[3]), "r"(b0), "r"(b1));
}
__device__ __forceinline__ float gelu_exact(float x) {
    return 0.5f * x * (1.0f + erff(x * 0.70710678118654752f));
}
__device__ __forceinline__ void cp16(unsigned* smem, const float* gmem) {
    unsigned saddr = (unsigned)__cvta_generic_to_shared(smem);
    asm volatile("cp.async.cg.shared.global [%0], [%1], 16;\n"
                 :: "r"(saddr), "l"(gmem));
}
__device__ __forceinline__ void cp_commit() {
    asm volatile("cp.async.commit_group;\n");
}
template<int N> __device__ __forceinline__ void cp_wait() {
    asm volatile("cp.async.wait_group %0;\n" :: "n"(N));
}

// ---------------- weight pre-rounding (RNA to tf32, stored as fp32) -------------
__global__ void round_tf32(const float* __restrict__ in, float* __restrict__ out,
                           int n4) {
    int i = blockIdx.x * 256 + threadIdx.x;
    if (i < n4) {
        float4 v = reinterpret_cast<const float4*>(in)[i];
        reinterpret_cast<float4*>(out)[i] =
            make_float4(rndf(v.x), rndf(v.y), rndf(v.z), rndf(v.w));
    }
}

// ---------------- LayerNorm: one block (128 thr) per token row; output rounded ----
__global__ void ln_kernel(const float* __restrict__ x, const float* __restrict__ w,
                          const float* __restrict__ b, float* __restrict__ out) {
    const int row = blockIdx.x;
    const int tid = threadIdx.x;
    const float4 v = reinterpret_cast<const float4*>(x + (size_t)row * DM)[tid];
    float s  = v.x + v.y + v.z + v.w;
    float ss = v.x*v.x + v.y*v.y + v.z*v.z + v.w*v.w;
    #pragma unroll
    for (int o = 16; o > 0; o >>= 1) {
        s  += __shfl_xor_sync(0xffffffffu, s,  o);
        ss += __shfl_xor_sync(0xffffffffu, ss, o);
    }
    __shared__ float sh[8];
    const int wid = tid >> 5;
    if ((tid & 31) == 0) { sh[wid] = s; sh[4 + wid] = ss; }
    __syncthreads();
    s  = sh[0] + sh[1] + sh[2] + sh[3];
    ss = sh[4] + sh[5] + sh[6] + sh[7];
    const float mean = s * (1.0f / DM);
    const float var  = ss * (1.0f / DM) - mean * mean;
    const float inv  = rsqrtf(var + 1e-5f);
    const float4 wv = reinterpret_cast<const float4*>(w)[tid];
    const float4 bv = reinterpret_cast<const float4*>(b)[tid];
    float4 o;
    o.x = rndf((v.x - mean) * inv * wv.x + bv.x);
    o.y = rndf((v.y - mean) * inv * wv.y + bv.y);
    o.z = rndf((v.z - mean) * inv * wv.z + bv.z);
    o.w = rndf((v.w - mean) * inv * wv.w + bv.w);
    reinterpret_cast<float4*>(out + (size_t)row * DM)[tid] = o;
}

// ---------------- tf32 GEMM, 3-stage cp.async, 128 thr, 2Mx2N warps ----------------
// C = A(MxK,lda) @ W(KxN) + bias [+C]; tile 128x128x32; warp tile 64x64.
// A and W must be tf32-representable fp32 (pre-rounded) — truncation is exact.
#define GA_W  (128 * 36)            // A stage words, stride 36 (≡4 mod 32)
#define GW_W  (32 * 136)            // W stage words, stride 136 (≡8 mod 32)
#define GSTG  (GA_W + GW_W)         // 8960 words per stage
#define GSMEM (3 * GSTG * 4)        // 107520 bytes

template<int MODE>  // 0: overwrite, 1: residual accumulate into C
__global__ void __launch_bounds__(128, 2) gemm_tf32(
    const float* __restrict__ A, const float* __restrict__ W,
    const float* __restrict__ bias, float* __restrict__ C,
    int N, int K, int lda) {
    extern __shared__ unsigned sm[];
    const int tid  = threadIdx.x;
    const int m0   = blockIdx.y * 128;
    const int n0   = blockIdx.x * 128;
    const int w    = tid >> 5, lane = tid & 31, gid = lane >> 2, tig = lane & 3;
    const int wm   = (w & 1) * 64, wn = (w >> 1) * 64;

    auto load_stage = [&](int s, int kb) {
        unsigned* As = sm + s * GSTG;
        unsigned* Ws = As + GA_W;
        #pragma unroll
        for (int j = 0; j < 8; j++) {
            int lin = tid + j * 128;
            int mm = lin >> 3, k4 = (lin & 7) << 2;
            cp16(&As[mm * 36 + k4], A + (size_t)(m0 + mm) * lda + kb + k4);
        }
        #pragma unroll
        for (int j = 0; j < 8; j++) {
            int lin = tid + j * 128;
            int kk = lin >> 5, n4 = (lin & 31) << 2;
            cp16(&Ws[kk * 136 + n4], W + (size_t)(kb + kk) * N + n0 + n4);
        }
    };

    float acc[4][8][4];
    #pragma unroll
    for (int i = 0; i < 4; i++)
        #pragma unroll
        for (int j = 0; j < 8; j++)
            #pragma unroll
            for (int r = 0; r < 4; r++) acc[i][j][r] = 0.0f;

    const int nk = K >> 5;
    load_stage(0, 0);  cp_commit();
    load_stage(1, 32); cp_commit();

    for (int it = 0; it < nk; it++) {
        cp_wait<1>();
        __syncthreads();
        const int nxt = it + 2;
        if (nxt < nk) load_stage(nxt % 3, nxt << 5);
        cp_commit();

        const unsigned* As = sm + (it % 3) * GSTG;
        const unsigned* Ws = As + GA_W;
        #pragma unroll
        for (int ks = 0; ks < 4; ks++) {
            const int k0 = ks * 8;
            unsigned a[4][4];
            #pragma unroll
            for (int mi = 0; mi < 4; mi++) {
                int r0 = wm + mi * 16 + gid;
                a[mi][0] = As[r0 * 36 + k0 + tig];
                a[mi][1] = As[(r0 + 8) * 36 + k0 + tig];
                a[mi][2] = As[r0 * 36 + k0 + tig + 4];
                a[mi][3] = As[(r0 + 8) * 36 + k0 + tig + 4];
            }
            #pragma unroll
            for (int ni = 0; ni < 8; ni++) {
                int cb = wn + ni * 8 + gid;
                unsigned b0 = Ws[(k0 + tig) * 136 + cb];
                unsigned b1 = Ws[(k0 + tig + 4) * 136 + cb];
                #pragma unroll
                for (int mi = 0; mi < 4; mi++) mma8(acc[mi][ni], a[mi], b0, b1);
            }
        }
    }

    #pragma unroll
    for (int mi = 0; mi < 4; mi++) {
        #pragma unroll
        for (int ni = 0; ni < 8; ni++) {
            int row = m0 + wm + mi * 16 + gid;
            int col = n0 + wn + ni * 8 + tig * 2;
            float2 bv = *reinterpret_cast<const float2*>(bias + col);
            float* p0 = C + (size_t)row * N + col;
            float* p1 = C + (size_t)(row + 8) * N + col;
            float v0 = acc[mi][ni][0] + bv.x, v1 = acc[mi][ni][1] + bv.y;
            float v2 = acc[mi][ni][2] + bv.x, v3 = acc[mi][ni][3] + bv.y;
            if (MODE == 1) {
                float2 o0 = *reinterpret_cast<float2*>(p0);
                float2 o1 = *reinterpret_cast<float2*>(p1);
                v0 += o0.x; v1 += o0.y; v2 += o1.x; v3 += o1.y;
            }
            *reinterpret_cast<float2*>(p0) = make_float2(v0, v1);
            *reinterpret_cast<float2*>(p1) = make_float2(v2, v3);
        }
    }
}

// ---------------- fused dual-GEMM + GLU, 128 thr, 2Mx2N warps ----------------
// G = gelu(A@Wp[:, :DFF]+bp1) * (A@Wp[:, DFF:]+bp2); tile 128 x (64 per half) x 32
#define LW_W  (32 * 72)             // each half-W stage words, stride 72 (≡8 mod 32)
#define LSTG  (GA_W + 2 * LW_W)     // 9216 words per stage
#define LSMEM (3 * LSTG * 4)        // 110592 bytes

__global__ void __launch_bounds__(128, 2) glu_gemm(
    const float* __restrict__ A, const float* __restrict__ Wp,
    const float* __restrict__ bp, float* __restrict__ G) {
    extern __shared__ unsigned sm[];
    const int tid = threadIdx.x;
    const int m0  = blockIdx.y * 128;
    const int n0  = blockIdx.x * 64;
    const int w   = tid >> 5, lane = tid & 31, gid = lane >> 2, tig = lane & 3;
    const int wm  = (w & 1) * 64, wn = (w >> 1) * 32;

    auto load_stage = [&](int s, int kb) {
        unsigned* As = sm + s * LSTG;
        unsigned* W1 = As + GA_W;
        unsigned* W2 = W1 + LW_W;
        #pragma unroll
        for (int j = 0; j < 8; j++) {
            int lin = tid + j * 128;
            int mm = lin >> 3, k4 = (lin & 7) << 2;
            cp16(&As[mm * 36 + k4], A + (size_t)(m0 + mm) * DM + kb + k4);
        }
        #pragma unroll
        for (int j = 0; j < 4; j++) {
            int lin = tid + j * 128;
            int kk = lin >> 4, n4 = (lin & 15) << 2;
            const float* wrow = Wp + (size_t)(kb + kk) * NN2 + n0 + n4;
            cp16(&W1[kk * 72 + n4], wrow);
            cp16(&W2[kk * 72 + n4], wrow + DFFN);
        }
    };

    float ac1[4][4][4], ac2[4][4][4];
    #pragma unroll
    for (int i = 0; i < 4; i++)
        #pragma unroll
        for (int j = 0; j < 4; j++)
            #pragma unroll
            for (int r = 0; r < 4; r++) { ac1[i][j][r] = 0.0f; ac2[i][j][r] = 0.0f; }

    const int nk = DM >> 5;   // 16
    load_stage(0, 0);  cp_commit();
    load_stage(1, 32); cp_commit();

    for (int it = 0; it < nk; it++) {
        cp_wait<1>();
        __syncthreads();
        const int nxt = it + 2;
        if (nxt < nk) load_stage(nxt % 3, nxt << 5);
        cp_commit();

        const unsigned* As = sm + (it % 3) * LSTG;
        const unsigned* W1 = As + GA_W;
        const unsigned* W2 = W1 + LW_W;
        #pragma unroll
        for (int ks = 0; ks < 4; ks++) {
            const int k0 = ks * 8;
            unsigned a[4][4];
            #pragma unroll
            for (int mi = 0; mi < 4; mi++) {
                int r0 = wm + mi * 16 + gid;
                a[mi][0] = As[r0 * 36 + k0 + tig];
                a[mi][1] = As[(r0 + 8) * 36 + k0 + tig];
                a[mi][2] = As[r0 * 36 + k0 + tig + 4];
                a[mi][3] = As[(r0 + 8) * 36 + k0 + tig + 4];
            }
            #pragma unroll
            for (int ni = 0; ni < 4; ni++) {
                int cb = wn + ni * 8 + gid;
                unsigned b0 = W1[(k0 + tig) * 72 + cb];
                unsigned b1 = W1[(k0 + tig + 4) * 72 + cb];
                #pragma unroll
                for (int mi = 0; mi < 4; mi++) mma8(ac1[mi][ni], a[mi], b0, b1);
                unsigned c0 = W2[(k0 + tig) * 72 + cb];
                unsigned c1 = W2[(k0 + tig + 4) * 72 + cb];
                #pragma unroll
                for (int mi = 0; mi < 4; mi++) mma8(ac2[mi][ni], a[mi], c0, c1);
            }
        }
    }

    #pragma unroll
    for (int mi = 0; mi < 4; mi++) {
        #pragma unroll
        for (int ni = 0; ni < 4; ni++) {
            int row = m0 + wm + mi * 16 + gid;
            int col = n0 + wn + ni * 8 + tig * 2;
            float2 b1 = *reinterpret_cast<const float2*>(bp + col);
            float2 b2 = *reinterpret_cast<const float2*>(bp + DFFN + col);
            float g0 = rndf(gelu_exact(ac1[mi][ni][0] + b1.x) * (ac2[mi][ni][0] + b2.x));
            float g1 = rndf(gelu_exact(ac1[mi][ni][1] + b1.y) * (ac2[mi][ni][1] + b2.y));
            float g2 = rndf(gelu_exact(ac1[mi][ni][2] + b1.x) * (ac2[mi][ni][2] + b2.x));
            float g3 = rndf(gelu_exact(ac1[mi][ni][3] + b1.y) * (ac2[mi][ni][3] + b2.y));
            *reinterpret_cast<float2*>(G + (size_t)row * DFFN + col)       = make_float2(g0, g1);
            *reinterpret_cast<float2*>(G + (size_t)(row + 8) * DFFN + col) = make_float2(g2, g3);
        }
    }
}

// ---------------- fused attention: one CTA per (b, h) ----------------
#define AST 68   // Q/K/P smem row stride (≡4 mod 32)
#define VST 72   // V smem row stride (≡8 mod 32)
#define ASMEM_WORDS (64*AST*3 + 64*VST + 240)
__global__ void __launch_bounds__(128) attn_kernel(
    const float* __restrict__ q, const float* __restrict__ k,
    const float* __restrict__ v, const float* __restrict__ tab,
    float* __restrict__ ctx) {
    extern __shared__ float smf[];
    unsigned* Qs = reinterpret_cast<unsigned*>(smf);
    unsigned* Ks = Qs + 64 * AST;
    unsigned* Vs = Ks + 64 * AST;
    float*    Ps = reinterpret_cast<float*>(Vs + 64 * VST);
    float*    Bs = Ps + 64 * AST;

    const int hh = blockIdx.x, bb = blockIdx.y;
    const int tid = threadIdx.x;
    const size_t base = ((size_t)bb * TN) * DM + hh * DKN;

    #pragma unroll
    for (int i = 0; i < 8; i++) {
        int lin = tid + i * 128;
        int t = lin >> 4, d4 = (lin & 15) << 2;
        float4 vq = *reinterpret_cast<const float4*>(q + base + (size_t)t * DM + d4);
        float4 vk = *reinterpret_cast<const float4*>(k + base + (size_t)t * DM + d4);
        float4 vv = *reinterpret_cast<const float4*>(v + base + (size_t)t * DM + d4);
        *reinterpret_cast<uint4*>(&Qs[t * AST + d4]) = cvt4(vq);
        *reinterpret_cast<uint4*>(&Ks[t * AST + d4]) = cvt4(vk);
        *reinterpret_cast<uint4*>(&Vs[t * VST + d4]) = cvt4(vv);
    }
    for (int i = tid; i < 225; i += 128)
        Bs[i] = 2.0f * tanhf(tab[(size_t)i * HN + hh]);
    __syncthreads();

    const int w = tid >> 5, lane = tid & 31, gid = lane >> 2, tig = lane & 3;

    // ---- S = Q K^T ----
    float sacc[8][4];
    #pragma unroll
    for (int i = 0; i < 8; i++)
        #pragma unroll
        for (int r = 0; r < 4; r++) sacc[i][r] = 0.0f;
    #pragma unroll
    for (int ks = 0; ks < 8; ks++) {
        const int k0 = ks * 8;
        unsigned a[4];
        a[0] = Qs[(w * 16 + gid) * AST + k0 + tig];
        a[1] = Qs[(w * 16 + gid + 8) * AST + k0 + tig];
        a[2] = Qs[(w * 16 + gid) * AST + k0 + tig + 4];
        a[3] = Qs[(w * 16 + gid + 8) * AST + k0 + tig + 4];
        #pragma unroll
        for (int ni = 0; ni < 8; ni++) {
            unsigned b0 = Ks[(ni * 8 + gid) * AST + k0 + tig];
            unsigned b1 = Ks[(ni * 8 + gid) * AST + k0 + tig + 4];
            mma8(sacc[ni], a, b0, b1);
        }
    }
    #pragma unroll
    for (int ni = 0; ni < 8; ni++) {
        int t0 = w * 16 + gid;
        int s0 = ni * 8 + tig * 2;
        #pragma unroll
        for (int r = 0; r < 4; r++) {
            int t = t0 + (r >> 1) * 8;
            int s = s0 + (r & 1);
            int idx = ((t >> 3) - (s >> 3) + 7) * 15 + (t & 7) - (s & 7) + 7;
            float val = sacc[ni][r] * 0.125f + Bs[idx];
            val = fminf(fmaxf(val, -50.0f), 50.0f);
            Ps[t * AST + s] = val;
        }
    }
    __syncthreads();

    // ---- softmax over s: 2 threads per row ----
    {
        int row = tid >> 1, hf = tid & 1;
        float* pr = Ps + row * AST + hf * 32;
        float mx = -1e30f;
        #pragma unroll
        for (int j = 0; j < 32; j++) mx = fmaxf(mx, pr[j]);
        mx = fmaxf(mx, __shfl_xor_sync(0xffffffffu, mx, 1));
        float sum = 0.0f;
        #pragma unroll
        for (int j = 0; j < 32; j++) { float e = __expf(pr[j] - mx); pr[j] = e; sum += e; }
        sum += __shfl_xor_sync(0xffffffffu, sum, 1);
        float inv = 1.0f / sum;
        unsigned* pu = reinterpret_cast<unsigned*>(pr);
        #pragma unroll
        for (int j = 0; j < 32; j++) pu[j] = f2tf(pr[j] * inv);
    }
    __syncthreads();

    // ---- ctx = P V ----
    const unsigned* Pu = reinterpret_cast<const unsigned*>(Ps);
    float cacc[8][4];
    #pragma unroll
    for (int i = 0; i < 8; i++)
        #pragma unroll
        for (int r = 0; r < 4; r++) cacc[i][r] = 0.0f;
    #pragma unroll
    for (int ks = 0; ks < 8; ks++) {
        const int k0 = ks * 8;
        unsigned a[4];
        a[0] = Pu[(w * 16 + gid) * AST + k0 + tig];
        a[1] = Pu[(w * 16 + gid + 8) * AST + k0 + tig];
        a[2] = Pu[(w * 16 + gid) * AST + k0 + tig + 4];
        a[3] = Pu[(w * 16 + gid + 8) * AST + k0 + tig + 4];
        #pragma unroll
        for (int ni = 0; ni < 8; ni++) {
            unsigned b0 = Vs[(k0 + tig) * VST + ni * 8 + gid];
            unsigned b1 = Vs[(k0 + tig + 4) * VST + ni * 8 + gid];
            mma8(cacc[ni], a, b0, b1);
        }
    }
    #pragma unroll
    for (int ni = 0; ni < 8; ni++) {
        int t0 = w * 16 + gid;
        int d0 = ni * 8 + tig * 2;
        *reinterpret_cast<float2*>(ctx + base + (size_t)t0 * DM + d0) =
            make_float2(rndf(cacc[ni][0]), rndf(cacc[ni][1]));
        *reinterpret_cast<float2*>(ctx + base + (size_t)(t0 + 8) * DM + d0) =
            make_float2(rndf(cacc[ni][2]), rndf(cacc[ni][3]));
    }
}

// ---------------- host orchestration ----------------
extern "C" void kernel_launch(void* const* d_in, const int* in_sizes, int n_in,
                              void* d_out, int out_size) {
    const float* x     = (const float*)d_in[0];
    const float* ln1w  = (const float*)d_in[1];
    const float* ln1b  = (const float*)d_in[2];
    const float* Wq    = (const float*)d_in[3];
    const float* bq    = (const float*)d_in[4];
    const float* Wk    = (const float*)d_in[5];
    const float* bk    = (const float*)d_in[6];
    const float* Wv    = (const float*)d_in[7];
    const float* bv    = (const float*)d_in[8];
    const float* Wo    = (const float*)d_in[9];
    const float* bo    = (const float*)d_in[10];
    const float* rel   = (const float*)d_in[11];
    const float* ln2w  = (const float*)d_in[12];
    const float* ln2b  = (const float*)d_in[13];
    const float* Wp    = (const float*)d_in[14];
    const float* bp    = (const float*)d_in[15];
    const float* Wf    = (const float*)d_in[16];
    const float* bf    = (const float*)d_in[17];

    float *h, *q, *k, *v, *c, *g;
    float *wq, *wk, *wv, *wo, *wp, *wf;
    cudaGetSymbolAddress((void**)&h, g_h);
    cudaGetSymbolAddress((void**)&q, g_q);
    cudaGetSymbolAddress((void**)&k, g_k);
    cudaGetSymbolAddress((void**)&v, g_v);
    cudaGetSymbolAddress((void**)&c, g_c);
    cudaGetSymbolAddress((void**)&g, g_g);
    cudaGetSymbolAddress((void**)&wq, g_wq);
    cudaGetSymbolAddress((void**)&wk, g_wk);
    cudaGetSymbolAddress((void**)&wv, g_wv);
    cudaGetSymbolAddress((void**)&wo, g_wo);
    cudaGetSymbolAddress((void**)&wp, g_wp);
    cudaGetSymbolAddress((void**)&wf, g_wf);

    const int asmem = ASMEM_WORDS * 4;
    cudaFuncSetAttribute(attn_kernel, cudaFuncAttributeMaxDynamicSharedMemorySize, asmem);
    cudaFuncSetAttribute(gemm_tf32<0>, cudaFuncAttributeMaxDynamicSharedMemorySize, GSMEM);
    cudaFuncSetAttribute(gemm_tf32<1>, cudaFuncAttributeMaxDynamicSharedMemorySize, GSMEM);
    cudaFuncSetAttribute(glu_gemm,     cudaFuncAttributeMaxDynamicSharedMemorySize, LSMEM);

    // pre-round all weights to tf32-representable fp32 (once per replay)
    {
        const int nQ = LNUM * DM * DM / 4;        // 851968
        const int nP = LNUM * DM * NN2 / 4;       // 6389760
        const int nF = LNUM * DFFN * DM / 4;      // 3194880
        round_tf32<<<(nQ + 255) / 256, 256>>>(Wq, wq, nQ);
        round_tf32<<<(nQ + 255) / 256, 256>>>(Wk, wk, nQ);
        round_tf32<<<(nQ + 255) / 256, 256>>>(Wv, wv, nQ);
        round_tf32<<<(nQ + 255) / 256, 256>>>(Wo, wo, nQ);
        round_tf32<<<(nP + 255) / 256, 256>>>(Wp, wp, nP);
        round_tf32<<<(nF + 255) / 256, 256>>>(Wf, wf, nF);
    }

    float* xb = (float*)d_out;  // fp32 residual stream lives in the output buffer
    cudaMemcpyAsync(xb, x, sizeof(float) * (size_t)MT * DM, cudaMemcpyDeviceToDevice);

    const dim3 gSq(DM / 128, MT / 128);     // (4, 256)
    const dim3 gGlu(DFFN / 64, MT / 128);   // (30, 256)
    const dim3 gAttn(HN, BN_);              // (8, 512)

    for (int l = 0; l < LNUM; l++) {
        const size_t lD  = (size_t)l * DM;
        const size_t lDD = (size_t)l * DM * DM;

        ln_kernel<<<MT, 128>>>(xb, ln1w + lD, ln1b + lD, h);
        gemm_tf32<0><<<gSq, 128, GSMEM>>>(h, wq + lDD, bq + lD, q, DM, DM, DM);
        gemm_tf32<0><<<gSq, 128, GSMEM>>>(h, wk + lDD, bk + lD, k, DM, DM, DM);
        gemm_tf32<0><<<gSq, 128, GSMEM>>>(h, wv + lDD, bv + lD, v, DM, DM, DM);
        attn_kernel<<<gAttn, 128, asmem>>>(q, k, v, rel + (size_t)l * 225 * HN, c);
        gemm_tf32<1><<<gSq, 128, GSMEM>>>(c, wo + lDD, bo + lD, xb, DM, DM, DM);

        ln_kernel<<<MT, 128>>>(xb, ln2w + lD, ln2b + lD, h);
        glu_gemm<<<gGlu, 128, LSMEM>>>(h, wp + (size_t)l * DM * NN2, bp + (size_t)l * NN2, g);
        gemm_tf32<1><<<gSq, 128, GSMEM>>>(g, wf + (size_t)l * DFFN * DM, bf + lD, xb,
                                          DM, DFFN, DFFN);
    }
}

// round 16
// speedup vs baseline: 1.3005x; 1.0007x over previous
#include <cuda_runtime.h>
#include <math.h>

// ---------------- problem constants ----------------
#define LNUM 13
#define DM   512
#define HN   8
#define DKN  64
#define DFFN 1920
#define NN2  (2*DFFN)
#define TN   64
#define BN_  512
#define MT   (BN_*TN)          // 32768 tokens

// ---------------- scratch (device globals; no allocs allowed) ----------------
__device__ float g_h[16777216];   // MT*DM   (post-LN activations, tf32-rounded)
__device__ float g_q[16777216];
__device__ float g_k[16777216];
__device__ float g_v[16777216];
__device__ float g_c[16777216];   // attention context (tf32-rounded)
__device__ float g_g[62914560];   // MT*DFFN (gated FFN intermediate, tf32-rounded)
// pre-rounded weights (tf32-representable fp32)
__device__ float g_wq[3407872];
__device__ float g_wk[3407872];
__device__ float g_wv[3407872];
__device__ float g_wo[3407872];
__device__ float g_wp[25559040];
__device__ float g_wf[12779520];

// ---------------- helpers ----------------
__device__ __forceinline__ unsigned f2tf(float x) {
    unsigned r; asm("cvt.rna.tf32.f32 %0, %1;" : "=r"(r) : "f"(x)); return r;
}
__device__ __forceinline__ float rndf(float x) { return __uint_as_float(f2tf(x)); }
__device__ __forceinline__ uint4 cvt4(float4 v) {
    return make_uint4(f2tf(v.x), f2tf(v.y), f2tf(v.z), f2tf(v.w));
}
__device__ __forceinline__ void mma8(float c[4], const unsigned a[4],
                                     unsigned b0, unsigned b1) {
    asm volatile(
        "mma.sync.aligned.m16n8k8.row.col.f32.tf32.tf32.f32 "
        "{%0,%1,%2,%3}, {%4,%5,%6,%7}, {%8,%9}, {%0,%1,%2,%3};\n"
        : "+f"(c[0]), "+f"(c[1]), "+f"(c[2]), "+f"(c[3])
        : "r"(a[0]), "r"(a[1]), "r"(a[2]), "r"(a[3]), "r"(b0), "r"(b1));
}
__device__ __forceinline__ float gelu_exact(float x) {
    return 0.5f * x * (1.0f + erff(x * 0.70710678118654752f));
}
__device__ __forceinline__ void cp16(unsigned* smem, const float* gmem) {
    unsigned saddr = (unsigned)__cvta_generic_to_shared(smem);
    asm volatile("cp.async.cg.shared.global [%0], [%1], 16;\n"
                 :: "r"(saddr), "l"(gmem));
}
__device__ __forceinline__ void cp_commit() {
    asm volatile("cp.async.commit_group;\n");
}
template<int N> __device__ __forceinline__ void cp_wait() {
    asm volatile("cp.async.wait_group %0;\n" :: "n"(N));
}

// ---------------- weight pre-rounding (RNA to tf32, stored as fp32) -------------
__global__ void round_tf32(const float* __restrict__ in, float* __restrict__ out,
                           int n4) {
    int i = blockIdx.x * 256 + threadIdx.x;
    if (i < n4) {
        float4 v = reinterpret_cast<const float4*>(in)[i];
        reinterpret_cast<float4*>(out)[i] =
            make_float4(rndf(v.x), rndf(v.y), rndf(v.z), rndf(v.w));
    }
}

// ---------------- LayerNorm: one block (128 thr) per token row; output rounded ----
__global__ void ln_kernel(const float* __restrict__ x, const float* __restrict__ w,
                          const float* __restrict__ b, float* __restrict__ out) {
    const int row = blockIdx.x;
    const int tid = threadIdx.x;
    const float4 v = reinterpret_cast<const float4*>(x + (size_t)row * DM)[tid];
    float s  = v.x + v.y + v.z + v.w;
    float ss = v.x*v.x + v.y*v.y + v.z*v.z + v.w*v.w;
    #pragma unroll
    for (int o = 16; o > 0; o >>= 1) {
        s  += __shfl_xor_sync(0xffffffffu, s,  o);
        ss += __shfl_xor_sync(0xffffffffu, ss, o);
    }
    __shared__ float sh[8];
    const int wid = tid >> 5;
    if ((tid & 31) == 0) { sh[wid] = s; sh[4 + wid] = ss; }
    __syncthreads();
    s  = sh[0] + sh[1] + sh[2] + sh[3];
    ss = sh[4] + sh[5] + sh[6] + sh[7];
    const float mean = s * (1.0f / DM);
    const float var  = ss * (1.0f / DM) - mean * mean;
    const float inv  = rsqrtf(var + 1e-5f);
    const float4 wv = reinterpret_cast<const float4*>(w)[tid];
    const float4 bv = reinterpret_cast<const float4*>(b)[tid];
    float4 o;
    o.x = rndf((v.x - mean) * inv * wv.x + bv.x);
    o.y = rndf((v.y - mean) * inv * wv.y + bv.y);
    o.z = rndf((v.z - mean) * inv * wv.z + bv.z);
    o.w = rndf((v.w - mean) * inv * wv.w + bv.w);
    reinterpret_cast<float4*>(out + (size_t)row * DM)[tid] = o;
}

// ---------------- tf32 GEMM, 3-stage cp.async, 128 thr, 2Mx2N warps ----------------
// C = A(MxK,lda) @ W(KxN) + bias [+C]; tile 128x128x32; warp tile 64x64.
// A and W must be tf32-representable fp32 (pre-rounded) — truncation is exact.
#define GA_W  (128 * 36)            // A stage words, stride 36 (≡4 mod 32)
#define GW_W  (32 * 136)            // W stage words, stride 136 (≡8 mod 32)
#define GSTG  (GA_W + GW_W)         // 8960 words per stage
#define GSMEM (3 * GSTG * 4)        // 107520 bytes

template<int MODE>  // 0: overwrite, 1: residual accumulate into C
__global__ void __launch_bounds__(128, 2) gemm_tf32(
    const float* __restrict__ A, const float* __restrict__ W,
    const float* __restrict__ bias, float* __restrict__ C,
    int N, int K, int lda) {
    extern __shared__ unsigned sm[];
    const int tid  = threadIdx.x;
    const int m0   = blockIdx.y * 128;
    const int n0   = blockIdx.x * 128;
    const int w    = tid >> 5, lane = tid & 31, gid = lane >> 2, tig = lane & 3;
    const int wm   = (w & 1) * 64, wn = (w >> 1) * 64;

    auto load_stage = [&](int s, int kb) {
        unsigned* As = sm + s * GSTG;
        unsigned* Ws = As + GA_W;
        #pragma unroll
        for (int j = 0; j < 8; j++) {
            int lin = tid + j * 128;
            int mm = lin >> 3, k4 = (lin & 7) << 2;
            cp16(&As[mm * 36 + k4], A + (size_t)(m0 + mm) * lda + kb + k4);
        }
        #pragma unroll
        for (int j = 0; j < 8; j++) {
            int lin = tid + j * 128;
            int kk = lin >> 5, n4 = (lin & 31) << 2;
            cp16(&Ws[kk * 136 + n4], W + (size_t)(kb + kk) * N + n0 + n4);
        }
    };

    float acc[4][8][4];
    #pragma unroll
    for (int i = 0; i < 4; i++)
        #pragma unroll
        for (int j = 0; j < 8; j++)
            #pragma unroll
            for (int r = 0; r < 4; r++) acc[i][j][r] = 0.0f;

    const int nk = K >> 5;
    load_stage(0, 0);  cp_commit();
    load_stage(1, 32); cp_commit();

    for (int it = 0; it < nk; it++) {
        cp_wait<1>();
        __syncthreads();
        const int nxt = it + 2;
        if (nxt < nk) load_stage(nxt % 3, nxt << 5);
        cp_commit();

        const unsigned* As = sm + (it % 3) * GSTG;
        const unsigned* Ws = As + GA_W;
        #pragma unroll
        for (int ks = 0; ks < 4; ks++) {
            const int k0 = ks * 8;
            unsigned a[4][4];
            #pragma unroll
            for (int mi = 0; mi < 4; mi++) {
                int r0 = wm + mi * 16 + gid;
                a[mi][0] = As[r0 * 36 + k0 + tig];
                a[mi][1] = As[(r0 + 8) * 36 + k0 + tig];
                a[mi][2] = As[r0 * 36 + k0 + tig + 4];
                a[mi][3] = As[(r0 + 8) * 36 + k0 + tig + 4];
            }
            #pragma unroll
            for (int ni = 0; ni < 8; ni++) {
                int cb = wn + ni * 8 + gid;
                unsigned b0 = Ws[(k0 + tig) * 136 + cb];
                unsigned b1 = Ws[(k0 + tig + 4) * 136 + cb];
                #pragma unroll
                for (int mi = 0; mi < 4; mi++) mma8(acc[mi][ni], a[mi], b0, b1);
            }
        }
    }

    #pragma unroll
    for (int mi = 0; mi < 4; mi++) {
        #pragma unroll
        for (int ni = 0; ni < 8; ni++) {
            int row = m0 + wm + mi * 16 + gid;
            int col = n0 + wn + ni * 8 + tig * 2;
            float2 bv = *reinterpret_cast<const float2*>(bias + col);
            float* p0 = C + (size_t)row * N + col;
            float* p1 = C + (size_t)(row + 8) * N + col;
            float v0 = acc[mi][ni][0] + bv.x, v1 = acc[mi][ni][1] + bv.y;
            float v2 = acc[mi][ni][2] + bv.x, v3 = acc[mi][ni][3] + bv.y;
            if (MODE == 1) {
                float2 o0 = *reinterpret_cast<float2*>(p0);
                float2 o1 = *reinterpret_cast<float2*>(p1);
                v0 += o0.x; v1 += o0.y; v2 += o1.x; v3 += o1.y;
            }
            *reinterpret_cast<float2*>(p0) = make_float2(v0, v1);
            *reinterpret_cast<float2*>(p1) = make_float2(v2, v3);
        }
    }
}

// ---------------- fused dual-GEMM + GLU, 128 thr, 2Mx2N warps ----------------
// G = gelu(A@Wp[:, :DFF]+bp1) * (A@Wp[:, DFF:]+bp2); tile 128 x (64 per half) x 32
#define LW_W  (32 * 72)             // each half-W stage words, stride 72 (≡8 mod 32)
#define LSTG  (GA_W + 2 * LW_W)     // 9216 words per stage
#define LSMEM (3 * LSTG * 4)        // 110592 bytes

__global__ void __launch_bounds__(128, 2) glu_gemm(
    const float* __restrict__ A, const float* __restrict__ Wp,
    const float* __restrict__ bp, float* __restrict__ G) {
    extern __shared__ unsigned sm[];
    const int tid = threadIdx.x;
    const int m0  = blockIdx.y * 128;
    const int n0  = blockIdx.x * 64;
    const int w   = tid >> 5, lane = tid & 31, gid = lane >> 2, tig = lane & 3;
    const int wm  = (w & 1) * 64, wn = (w >> 1) * 32;

    auto load_stage = [&](int s, int kb) {
        unsigned* As = sm + s * LSTG;
        unsigned* W1 = As + GA_W;
        unsigned* W2 = W1 + LW_W;
        #pragma unroll
        for (int j = 0; j < 8; j++) {
            int lin = tid + j * 128;
            int mm = lin >> 3, k4 = (lin & 7) << 2;
            cp16(&As[mm * 36 + k4], A + (size_t)(m0 + mm) * DM + kb + k4);
        }
        #pragma unroll
        for (int j = 0; j < 4; j++) {
            int lin = tid + j * 128;
            int kk = lin >> 4, n4 = (lin & 15) << 2;
            const float* wrow = Wp + (size_t)(kb + kk) * NN2 + n0 + n4;
            cp16(&W1[kk * 72 + n4], wrow);
            cp16(&W2[kk * 72 + n4], wrow + DFFN);
        }
    };

    float ac1[4][4][4], ac2[4][4][4];
    #pragma unroll
    for (int i = 0; i < 4; i++)
        #pragma unroll
        for (int j = 0; j < 4; j++)
            #pragma unroll
            for (int r = 0; r < 4; r++) { ac1[i][j][r] = 0.0f; ac2[i][j][r] = 0.0f; }

    const int nk = DM >> 5;   // 16
    load_stage(0, 0);  cp_commit();
    load_stage(1, 32); cp_commit();

    for (int it = 0; it < nk; it++) {
        cp_wait<1>();
        __syncthreads();
        const int nxt = it + 2;
        if (nxt < nk) load_stage(nxt % 3, nxt << 5);
        cp_commit();

        const unsigned* As = sm + (it % 3) * LSTG;
        const unsigned* W1 = As + GA_W;
        const unsigned* W2 = W1 + LW_W;
        #pragma unroll
        for (int ks = 0; ks < 4; ks++) {
            const int k0 = ks * 8;
            unsigned a[4][4];
            #pragma unroll
            for (int mi = 0; mi < 4; mi++) {
                int r0 = wm + mi * 16 + gid;
                a[mi][0] = As[r0 * 36 + k0 + tig];
                a[mi][1] = As[(r0 + 8) * 36 + k0 + tig];
                a[mi][2] = As[r0 * 36 + k0 + tig + 4];
                a[mi][3] = As[(r0 + 8) * 36 + k0 + tig + 4];
            }
            #pragma unroll
            for (int ni = 0; ni < 4; ni++) {
                int cb = wn + ni * 8 + gid;
                unsigned b0 = W1[(k0 + tig) * 72 + cb];
                unsigned b1 = W1[(k0 + tig + 4) * 72 + cb];
                #pragma unroll
                for (int mi = 0; mi < 4; mi++) mma8(ac1[mi][ni], a[mi], b0, b1);
                unsigned c0 = W2[(k0 + tig) * 72 + cb];
                unsigned c1 = W2[(k0 + tig + 4) * 72 + cb];
                #pragma unroll
                for (int mi = 0; mi < 4; mi++) mma8(ac2[mi][ni], a[mi], c0, c1);
            }
        }
    }

    #pragma unroll
    for (int mi = 0; mi < 4; mi++) {
        #pragma unroll
        for (int ni = 0; ni < 4; ni++) {
            int row = m0 + wm + mi * 16 + gid;
            int col = n0 + wn + ni * 8 + tig * 2;
            float2 b1 = *reinterpret_cast<const float2*>(bp + col);
            float2 b2 = *reinterpret_cast<const float2*>(bp + DFFN + col);
            float g0 = rndf(gelu_exact(ac1[mi][ni][0] + b1.x) * (ac2[mi][ni][0] + b2.x));
            float g1 = rndf(gelu_exact(ac1[mi][ni][1] + b1.y) * (ac2[mi][ni][1] + b2.y));
            float g2 = rndf(gelu_exact(ac1[mi][ni][2] + b1.x) * (ac2[mi][ni][2] + b2.x));
            float g3 = rndf(gelu_exact(ac1[mi][ni][3] + b1.y) * (ac2[mi][ni][3] + b2.y));
            *reinterpret_cast<float2*>(G + (size_t)row * DFFN + col)       = make_float2(g0, g1);
            *reinterpret_cast<float2*>(G + (size_t)(row + 8) * DFFN + col) = make_float2(g2, g3);
        }
    }
}

// ---------------- fused attention: one CTA per (b, h) ----------------
#define AST 68   // Q/K/P smem row stride (≡4 mod 32)
#define VST 72   // V smem row stride (≡8 mod 32)
#define ASMEM_WORDS (64*AST*3 + 64*VST + 240)
__global__ void __launch_bounds__(128) attn_kernel(
    const float* __restrict__ q, const float* __restrict__ k,
    const float* __restrict__ v, const float* __restrict__ tab,
    float* __restrict__ ctx) {
    extern __shared__ float smf[];
    unsigned* Qs = reinterpret_cast<unsigned*>(smf);
    unsigned* Ks = Qs + 64 * AST;
    unsigned* Vs = Ks + 64 * AST;
    float*    Ps = reinterpret_cast<float*>(Vs + 64 * VST);
    float*    Bs = Ps + 64 * AST;

    const int hh = blockIdx.x, bb = blockIdx.y;
    const int tid = threadIdx.x;
    const size_t base = ((size_t)bb * TN) * DM + hh * DKN;

    #pragma unroll
    for (int i = 0; i < 8; i++) {
        int lin = tid + i * 128;
        int t = lin >> 4, d4 = (lin & 15) << 2;
        float4 vq = *reinterpret_cast<const float4*>(q + base + (size_t)t * DM + d4);
        float4 vk = *reinterpret_cast<const float4*>(k + base + (size_t)t * DM + d4);
        float4 vv = *reinterpret_cast<const float4*>(v + base + (size_t)t * DM + d4);
        *reinterpret_cast<uint4*>(&Qs[t * AST + d4]) = cvt4(vq);
        *reinterpret_cast<uint4*>(&Ks[t * AST + d4]) = cvt4(vk);
        *reinterpret_cast<uint4*>(&Vs[t * VST + d4]) = cvt4(vv);
    }
    for (int i = tid; i < 225; i += 128)
        Bs[i] = 2.0f * tanhf(tab[(size_t)i * HN + hh]);
    __syncthreads();

    const int w = tid >> 5, lane = tid & 31, gid = lane >> 2, tig = lane & 3;

    // ---- S = Q K^T ----
    float sacc[8][4];
    #pragma unroll
    for (int i = 0; i < 8; i++)
        #pragma unroll
        for (int r = 0; r < 4; r++) sacc[i][r] = 0.0f;
    #pragma unroll
    for (int ks = 0; ks < 8; ks++) {
        const int k0 = ks * 8;
        unsigned a[4];
        a[0] = Qs[(w * 16 + gid) * AST + k0 + tig];
        a[1] = Qs[(w * 16 + gid + 8) * AST + k0 + tig];
        a[2] = Qs[(w * 16 + gid) * AST + k0 + tig + 4];
        a[3] = Qs[(w * 16 + gid + 8) * AST + k0 + tig + 4];
        #pragma unroll
        for (int ni = 0; ni < 8; ni++) {
            unsigned b0 = Ks[(ni * 8 + gid) * AST + k0 + tig];
            unsigned b1 = Ks[(ni * 8 + gid) * AST + k0 + tig + 4];
            mma8(sacc[ni], a, b0, b1);
        }
    }
    #pragma unroll
    for (int ni = 0; ni < 8; ni++) {
        int t0 = w * 16 + gid;
        int s0 = ni * 8 + tig * 2;
        #pragma unroll
        for (int r = 0; r < 4; r++) {
            int t = t0 + (r >> 1) * 8;
            int s = s0 + (r & 1);
            int idx = ((t >> 3) - (s >> 3) + 7) * 15 + (t & 7) - (s & 7) + 7;
            float val = sacc[ni][r] * 0.125f + Bs[idx];
            val = fminf(fmaxf(val, -50.0f), 50.0f);
            Ps[t * AST + s] = val;
        }
    }
    __syncthreads();

    // ---- softmax over s: 2 threads per row ----
    {
        int row = tid >> 1, hf = tid & 1;
        float* pr = Ps + row * AST + hf * 32;
        float mx = -1e30f;
        #pragma unroll
        for (int j = 0; j < 32; j++) mx = fmaxf(mx, pr[j]);
        mx = fmaxf(mx, __shfl_xor_sync(0xffffffffu, mx, 1));
        float sum = 0.0f;
        #pragma unroll
        for (int j = 0; j < 32; j++) { float e = __expf(pr[j] - mx); pr[j] = e; sum += e; }
        sum += __shfl_xor_sync(0xffffffffu, sum, 1);
        float inv = 1.0f / sum;
        unsigned* pu = reinterpret_cast<unsigned*>(pr);
        #pragma unroll
        for (int j = 0; j < 32; j++) pu[j] = f2tf(pr[j] * inv);
    }
    __syncthreads();

    // ---- ctx = P V ----
    const unsigned* Pu = reinterpret_cast<const unsigned*>(Ps);
    float cacc[8][4];
    #pragma unroll
    for (int i = 0; i < 8; i++)
        #pragma unroll
        for (int r = 0; r < 4; r++) cacc[i][r] = 0.0f;
    #pragma unroll
    for (int ks = 0; ks < 8; ks++) {
        const int k0 = ks * 8;
        unsigned a[4];
        a[0] = Pu[(w * 16 + gid) * AST + k0 + tig];
        a[1] = Pu[(w * 16 + gid + 8) * AST + k0 + tig];
        a[2] = Pu[(w * 16 + gid) * AST + k0 + tig + 4];
        a[3] = Pu[(w * 16 + gid + 8) * AST + k0 + tig + 4];
        #pragma unroll
        for (int ni = 0; ni < 8; ni++) {
            unsigned b0 = Vs[(k0 + tig) * VST + ni * 8 + gid];
            unsigned b1 = Vs[(k0 + tig + 4) * VST + ni * 8 + gid];
            mma8(cacc[ni], a, b0, b1);
        }
    }
    #pragma unroll
    for (int ni = 0; ni < 8; ni++) {
        int t0 = w * 16 + gid;
        int d0 = ni * 8 + tig * 2;
        *reinterpret_cast<float2*>(ctx + base + (size_t)t0 * DM + d0) =
            make_float2(rndf(cacc[ni][0]), rndf(cacc[ni][1]));
        *reinterpret_cast<float2*>(ctx + base + (size_t)(t0 + 8) * DM + d0) =
            make_float2(rndf(cacc[ni][2]), rndf(cacc[ni][3]));
    }
}

// ---------------- host orchestration ----------------
extern "C" void kernel_launch(void* const* d_in, const int* in_sizes, int n_in,
                              void* d_out, int out_size) {
    const float* x     = (const float*)d_in[0];
    const float* ln1w  = (const float*)d_in[1];
    const float* ln1b  = (const float*)d_in[2];
    const float* Wq    = (const float*)d_in[3];
    const float* bq    = (const float*)d_in[4];
    const float* Wk    = (const float*)d_in[5];
    const float* bk    = (const float*)d_in[6];
    const float* Wv    = (const float*)d_in[7];
    const float* bv    = (const float*)d_in[8];
    const float* Wo    = (const float*)d_in[9];
    const float* bo    = (const float*)d_in[10];
    const float* rel   = (const float*)d_in[11];
    const float* ln2w  = (const float*)d_in[12];
    const float* ln2b  = (const float*)d_in[13];
    const float* Wp    = (const float*)d_in[14];
    const float* bp    = (const float*)d_in[15];
    const float* Wf    = (const float*)d_in[16];
    const float* bf    = (const float*)d_in[17];

    float *h, *q, *k, *v, *c, *g;
    float *wq, *wk, *wv, *wo, *wp, *wf;
    cudaGetSymbolAddress((void**)&h, g_h);
    cudaGetSymbolAddress((void**)&q, g_q);
    cudaGetSymbolAddress((void**)&k, g_k);
    cudaGetSymbolAddress((void**)&v, g_v);
    cudaGetSymbolAddress((void**)&c, g_c);
    cudaGetSymbolAddress((void**)&g, g_g);
    cudaGetSymbolAddress((void**)&wq, g_wq);
    cudaGetSymbolAddress((void**)&wk, g_wk);
    cudaGetSymbolAddress((void**)&wv, g_wv);
    cudaGetSymbolAddress((void**)&wo, g_wo);
    cudaGetSymbolAddress((void**)&wp, g_wp);
    cudaGetSymbolAddress((void**)&wf, g_wf);

    const int asmem = ASMEM_WORDS * 4;
    cudaFuncSetAttribute(attn_kernel, cudaFuncAttributeMaxDynamicSharedMemorySize, asmem);
    cudaFuncSetAttribute(gemm_tf32<0>, cudaFuncAttributeMaxDynamicSharedMemorySize, GSMEM);
    cudaFuncSetAttribute(gemm_tf32<1>, cudaFuncAttributeMaxDynamicSharedMemorySize, GSMEM);
    cudaFuncSetAttribute(glu_gemm,     cudaFuncAttributeMaxDynamicSharedMemorySize, LSMEM);

    // pre-round all weights to tf32-representable fp32 (once per replay)
    {
        const int nQ = LNUM * DM * DM / 4;        // 851968
        const int nP = LNUM * DM * NN2 / 4;       // 6389760
        const int nF = LNUM * DFFN * DM / 4;      // 3194880
        round_tf32<<<(nQ + 255) / 256, 256>>>(Wq, wq, nQ);
        round_tf32<<<(nQ + 255) / 256, 256>>>(Wk, wk, nQ);
        round_tf32<<<(nQ + 255) / 256, 256>>>(Wv, wv, nQ);
        round_tf32<<<(nQ + 255) / 256, 256>>>(Wo, wo, nQ);
        round_tf32<<<(nP + 255) / 256, 256>>>(Wp, wp, nP);
        round_tf32<<<(nF + 255) / 256, 256>>>(Wf, wf, nF);
    }

    float* xb = (float*)d_out;  // fp32 residual stream lives in the output buffer
    cudaMemcpyAsync(xb, x, sizeof(float) * (size_t)MT * DM, cudaMemcpyDeviceToDevice);

    const dim3 gSq(DM / 128, MT / 128);     // (4, 256)
    const dim3 gGlu(DFFN / 64, MT / 128);   // (30, 256)
    const dim3 gAttn(HN, BN_);              // (8, 512)

    for (int l = 0; l < LNUM; l++) {
        const size_t lD  = (size_t)l * DM;
        const size_t lDD = (size_t)l * DM * DM;

        ln_kernel<<<MT, 128>>>(xb, ln1w + lD, ln1b + lD, h);
        gemm_tf32<0><<<gSq, 128, GSMEM>>>(h, wq + lDD, bq + lD, q, DM, DM, DM);
        gemm_tf32<0><<<gSq, 128, GSMEM>>>(h, wk + lDD, bk + lD, k, DM, DM, DM);
        gemm_tf32<0><<<gSq, 128, GSMEM>>>(h, wv + lDD, bv + lD, v, DM, DM, DM);
        attn_kernel<<<gAttn, 128, asmem>>>(q, k, v, rel + (size_t)l * 225 * HN, c);
        gemm_tf32<1><<<gSq, 128, GSMEM>>>(c, wo + lDD, bo + lD, xb, DM, DM, DM);

        ln_kernel<<<MT, 128>>>(xb, ln2w + lD, ln2b + lD, h);
        glu_gemm<<<gGlu, 128, LSMEM>>>(h, wp + (size_t)l * DM * NN2, bp + (size_t)l * NN2, g);
        gemm_tf32<1><<<gSq, 128, GSMEM>>>(g, wf + (size_t)l * DFFN * DM, bf + lD, xb,
                                          DM, DFFN, DFFN);
    }
}